// round 6
// baseline (speedup 1.0000x reference)
#include <cuda_runtime.h>
#include <math.h>
#include <stdint.h>

// Problem shape (fixed)
static constexpr int Bb = 4;
static constexpr int Tt = 2048;
static constexpr int Dd = 1024;
static constexpr int Hh = 16;
static constexpr int HDd = 64;
static constexpr int DFf = 4096;
static constexpr int Mrows = Bb * Tt;   // 8192

// ---------------- scratch (device globals; no allocation allowed) ----------
__device__ float g_Q[(size_t)Mrows * Dd];
__device__ float g_K[(size_t)Mrows * Dd];
__device__ float g_V[(size_t)Mrows * Dd];
__device__ float g_attn[(size_t)Mrows * Dd];
__device__ float g_proj[(size_t)Mrows * Dd];
__device__ float g_h[(size_t)Mrows * Dd];
__device__ float g_ff1[(size_t)Mrows * DFf];
__device__ float g_ff2[(size_t)Mrows * Dd];

// ---------------- helpers ----------------
__device__ __forceinline__ float gelu_exact(float x) {
    return 0.5f * x * (1.0f + erff(x * 0.70710678118654752f));
}

// mma consumes raw fp32 bits as tf32 (HW truncates low mantissa bits).
__device__ __forceinline__ void mma_tf32(
    float& c0, float& c1, float& c2, float& c3,
    uint32_t a0, uint32_t a1, uint32_t a2, uint32_t a3,
    uint32_t b0, uint32_t b1)
{
    asm volatile(
        "mma.sync.aligned.m16n8k8.row.col.f32.tf32.tf32.f32 "
        "{%0,%1,%2,%3}, {%4,%5,%6,%7}, {%8,%9}, {%0,%1,%2,%3};\n"
        : "+f"(c0), "+f"(c1), "+f"(c2), "+f"(c3)
        : "r"(a0), "r"(a1), "r"(a2), "r"(a3), "r"(b0), "r"(b1));
}

__device__ __forceinline__ void cp_async16(uint32_t smem_addr, const void* gptr) {
    asm volatile("cp.async.cg.shared.global [%0], [%1], 16;\n"
                 :: "r"(smem_addr), "l"(gptr));
}
__device__ __forceinline__ void cp_commit() {
    asm volatile("cp.async.commit_group;\n");
}
template <int N>
__device__ __forceinline__ void cp_wait() {
    asm volatile("cp.async.wait_group %0;\n" :: "n"(N));
}

// ---------------- tf32 tensor-core GEMM, cp.async 4-stage -------------------
// C[M,N] = A[M,K] @ B[K,N] (+bias)(+gelu)
// Block 128x256, BK=16, 256 threads (8 warps), warp tile 64x64.
static constexpr int AS_STRIDE = 20;    // 16 k + 4 pad (words)
static constexpr int BS_STRIDE = 264;   // 256 n + 8 pad
static constexpr int ASZ = 128 * AS_STRIDE;          // 2560 words per A stage
static constexpr int BSZ = 16 * BS_STRIDE;           // 4224 words per B stage
static constexpr int STAGE_W = ASZ + BSZ;            // 6784
static constexpr int GSTAGES = 4;
static constexpr int GEMM_SMEM = GSTAGES * STAGE_W * 4;   // 108544 B

template <int EPI>
__global__ __launch_bounds__(256) void gemm_cp_kernel(
    const float* __restrict__ A, const float* __restrict__ Bm,
    const float* __restrict__ bias, float* __restrict__ C,
    int M, int N, int K)
{
    extern __shared__ uint32_t sh[];
    const uint32_t sbase = (uint32_t)__cvta_generic_to_shared(sh);

    const int tid = threadIdx.x;
    const int warp = tid >> 5;
    const int lane = tid & 31;
    const int lq = lane >> 2;
    const int lr = lane & 3;

    const int bm = blockIdx.y * 128;
    const int bn = blockIdx.x * 256;
    const int wm = (warp & 1) * 64;
    const int wn = (warp >> 1) * 64;

    // A tile: 128x16 = 512 float4, 2 per thread
    const int a_row0 = tid >> 2;              // 0..63
    const int a_row1 = (tid + 256) >> 2;      // 64..127
    const int a_c4   = (tid & 3) * 4;
    // B tile: 16x256 = 1024 float4, 4 per thread
    int b_row[4], b_n4[4];
#pragma unroll
    for (int it = 0; it < 4; it++) {
        const int id = tid + it * 256;
        b_row[it] = id >> 6;            // 0..15
        b_n4[it] = (id & 63) * 4;       // 0..252
    }

    const float* Ag = A + (size_t)bm * K;
    const float* Bg = Bm + bn;

    const uint32_t sa0 = (a_row0 * AS_STRIDE + a_c4) * 4;
    const uint32_t sa1 = (a_row1 * AS_STRIDE + a_c4) * 4;
    uint32_t sb[4];
#pragma unroll
    for (int it = 0; it < 4; it++)
        sb[it] = (ASZ + b_row[it] * BS_STRIDE + b_n4[it]) * 4;

    const int KT = K / 16;

    auto issue = [&](int kt, int stage) {
        const uint32_t st = sbase + (uint32_t)(stage * STAGE_W * 4);
        const int k0 = kt * 16;
        cp_async16(st + sa0, Ag + (size_t)a_row0 * K + k0 + a_c4);
        cp_async16(st + sa1, Ag + (size_t)a_row1 * K + k0 + a_c4);
#pragma unroll
        for (int it = 0; it < 4; it++)
            cp_async16(st + sb[it], Bg + (size_t)(k0 + b_row[it]) * N + b_n4[it]);
    };

    // prologue: 3 tiles in flight
#pragma unroll
    for (int s = 0; s < GSTAGES - 1; s++) {
        issue(s, s);
        cp_commit();
    }

    float acc[4][8][4];
#pragma unroll
    for (int i = 0; i < 4; i++)
#pragma unroll
        for (int j = 0; j < 8; j++)
#pragma unroll
            for (int r = 0; r < 4; r++) acc[i][j][r] = 0.0f;

    for (int it = 0; it < KT; ++it) {
        cp_wait<GSTAGES - 2>();   // tile `it` resident
        __syncthreads();          // publish; stage (it-1)&3 free
        if (it + GSTAGES - 1 < KT) issue(it + GSTAGES - 1, (it + GSTAGES - 1) & 3);
        cp_commit();

        const uint32_t* Asb = sh + (it & 3) * STAGE_W;
        const uint32_t* Bsb = Asb + ASZ;
#pragma unroll
        for (int kk = 0; kk < 16; kk += 8) {
            uint32_t af[4][4];
#pragma unroll
            for (int mt = 0; mt < 4; mt++) {
                const int r0 = wm + mt * 16 + lq;
                af[mt][0] = Asb[r0 * AS_STRIDE + kk + lr];
                af[mt][1] = Asb[(r0 + 8) * AS_STRIDE + kk + lr];
                af[mt][2] = Asb[r0 * AS_STRIDE + kk + lr + 4];
                af[mt][3] = Asb[(r0 + 8) * AS_STRIDE + kk + lr + 4];
            }
            uint32_t bf[8][2];
#pragma unroll
            for (int nt = 0; nt < 8; nt++) {
                const int c0 = wn + nt * 8 + lq;
                bf[nt][0] = Bsb[(kk + lr) * BS_STRIDE + c0];
                bf[nt][1] = Bsb[(kk + lr + 4) * BS_STRIDE + c0];
            }
#pragma unroll
            for (int mt = 0; mt < 4; mt++)
#pragma unroll
                for (int nt = 0; nt < 8; nt++)
                    mma_tf32(acc[mt][nt][0], acc[mt][nt][1],
                             acc[mt][nt][2], acc[mt][nt][3],
                             af[mt][0], af[mt][1], af[mt][2], af[mt][3],
                             bf[nt][0], bf[nt][1]);
        }
    }

    // ---- epilogue ----
#pragma unroll
    for (int mt = 0; mt < 4; mt++) {
#pragma unroll
        for (int nt = 0; nt < 8; nt++) {
            const int col = bn + wn + nt * 8 + 2 * lr;
#pragma unroll
            for (int half = 0; half < 2; half++) {
                const int row = bm + wm + mt * 16 + lq + half * 8;
                float v0 = acc[mt][nt][half * 2 + 0];
                float v1 = acc[mt][nt][half * 2 + 1];
                if (EPI >= 1) {
                    v0 += bias[col];
                    v1 += bias[col + 1];
                }
                if (EPI == 2) {
                    v0 = gelu_exact(v0);
                    v1 = gelu_exact(v1);
                }
                *(float2*)&C[(size_t)row * N + col] = make_float2(v0, v1);
            }
        }
    }
}

// ---------------- tensor-core flash attention, cp.async double-buffer -------
// Block: 128 q-rows x one (b,h). 8 warps; warp owns 16 q-rows. KV tile = 64.
static constexpr int KS_ST = 68;
static constexpr int VS_ST = 72;
static constexpr int PS_ST = 68;
static constexpr int KBUF = 64 * KS_ST;    // words
static constexpr int VBUF = 64 * VS_ST;
static constexpr int FLASH_SMEM = (2 * KBUF + 2 * VBUF + 128 * PS_ST) * 4; // 106496 B

__global__ __launch_bounds__(256) void flash_tc_kernel(
    const float* __restrict__ Qb, const float* __restrict__ Kb,
    const float* __restrict__ Vb, float* __restrict__ Ob)
{
    extern __shared__ uint32_t smu[];
    uint32_t* Ks[2] = { smu, smu + KBUF };
    uint32_t* Vs[2] = { smu + 2 * KBUF, smu + 2 * KBUF + VBUF };
    uint32_t* Ps = smu + 2 * KBUF + 2 * VBUF;
    float*    Psf = (float*)Ps;
    const uint32_t sbase = (uint32_t)__cvta_generic_to_shared(smu);

    const int tid = threadIdx.x;
    const int warp = tid >> 5;
    const int lane = tid & 31;
    const int lq = lane >> 2;   // 0..7
    const int lr = lane & 3;    // 0..3

    const int b = blockIdx.y / Hh;
    const int h = blockIdx.y % Hh;
    const int q0 = blockIdx.x * 128;
    const int w16 = warp * 16;

    const float scale = 0.125f;   // folded into Q fragments (exact: power of 2)

    int kv_r[4], kv_c4[4];
#pragma unroll
    for (int it = 0; it < 4; it++) {
        const int id = tid + it * 256;
        kv_r[it] = id >> 4;
        kv_c4[it] = (id & 15) << 2;
    }

    auto issue_kv = [&](int kv_tile, int buf) {
        const size_t baseKV = ((size_t)(b * Tt + kv_tile * 64)) * Dd + h * HDd;
        const uint32_t kst = sbase + (uint32_t)(buf * KBUF * 4);
        const uint32_t vst = sbase + (uint32_t)((2 * KBUF + buf * VBUF) * 4);
#pragma unroll
        for (int it = 0; it < 4; it++) {
            const size_t g = baseKV + (size_t)kv_r[it] * Dd + kv_c4[it];
            cp_async16(kst + (kv_r[it] * KS_ST + kv_c4[it]) * 4, Kb + g);
            cp_async16(vst + (kv_r[it] * VS_ST + kv_c4[it]) * 4, Vb + g);
        }
    };

    // prefetch KV tile 0 while staging Q
    issue_kv(0, 0);
    cp_commit();

    // ---- stage Q tile [128 x 64] into Psf (coalesced) ----
    {
        const size_t baseQ = ((size_t)(b * Tt + q0)) * Dd + h * HDd;
#pragma unroll
        for (int it = 0; it < 8; it++) {
            const int id = tid + it * 256;
            const int r = id >> 4, c4 = (id & 15) << 2;
            float4 v = *(const float4*)&Qb[baseQ + (size_t)r * Dd + c4];
            float* p = &Psf[r * PS_ST + c4];
            p[0] = v.x; p[1] = v.y; p[2] = v.z; p[3] = v.w;
        }
    }
    __syncthreads();

    // ---- Q fragments (pre-scaled, raw fp32 bits) held in registers ----
    uint32_t qa[8][4];
#pragma unroll
    for (int kk8 = 0; kk8 < 8; kk8++) {
        const int c = kk8 * 8;
        qa[kk8][0] = __float_as_uint(Psf[(w16 + lq) * PS_ST + c + lr] * scale);
        qa[kk8][1] = __float_as_uint(Psf[(w16 + lq + 8) * PS_ST + c + lr] * scale);
        qa[kk8][2] = __float_as_uint(Psf[(w16 + lq) * PS_ST + c + lr + 4] * scale);
        qa[kk8][3] = __float_as_uint(Psf[(w16 + lq + 8) * PS_ST + c + lr + 4] * scale);
    }
    __syncthreads();   // Q frags read before Ps reused for P

    float o[8][4];
#pragma unroll
    for (int nt = 0; nt < 8; nt++)
#pragma unroll
        for (int r = 0; r < 4; r++) o[nt][r] = 0.0f;
    float m0 = -INFINITY, m1 = -INFINITY;
    float l0 = 0.0f, l1 = 0.0f;

    const int NT = Tt / 64;   // 32
    for (int t = 0; t < NT; ++t) {
        if (t + 1 < NT) issue_kv(t + 1, (t + 1) & 1);
        cp_commit();
        cp_wait<1>();      // tile t resident
        __syncthreads();

        const uint32_t* Kst = Ks[t & 1];
        const uint32_t* Vst = Vs[t & 1];

        // ---- S = (Q*scale) K^T ----
        float s[8][4];
#pragma unroll
        for (int nt = 0; nt < 8; nt++)
#pragma unroll
            for (int r = 0; r < 4; r++) s[nt][r] = 0.0f;

#pragma unroll
        for (int kk8 = 0; kk8 < 8; kk8++) {
            const int c = kk8 * 8;
#pragma unroll
            for (int nt = 0; nt < 8; nt++) {
                const uint32_t b0 = Kst[(nt * 8 + lq) * KS_ST + c + lr];
                const uint32_t b1 = Kst[(nt * 8 + lq) * KS_ST + c + lr + 4];
                mma_tf32(s[nt][0], s[nt][1], s[nt][2], s[nt][3],
                         qa[kk8][0], qa[kk8][1], qa[kk8][2], qa[kk8][3],
                         b0, b1);
            }
        }

        // ---- online softmax (scores already scaled) ----
        float rm0 = -INFINITY, rm1 = -INFINITY;
#pragma unroll
        for (int nt = 0; nt < 8; nt++) {
            rm0 = fmaxf(rm0, fmaxf(s[nt][0], s[nt][1]));
            rm1 = fmaxf(rm1, fmaxf(s[nt][2], s[nt][3]));
        }
        rm0 = fmaxf(rm0, __shfl_xor_sync(0xffffffffu, rm0, 1));
        rm0 = fmaxf(rm0, __shfl_xor_sync(0xffffffffu, rm0, 2));
        rm1 = fmaxf(rm1, __shfl_xor_sync(0xffffffffu, rm1, 1));
        rm1 = fmaxf(rm1, __shfl_xor_sync(0xffffffffu, rm1, 2));
        const float mn0 = fmaxf(m0, rm0);
        const float mn1 = fmaxf(m1, rm1);
        const float alpha0 = __expf(m0 - mn0);
        const float alpha1 = __expf(m1 - mn1);

        float rs0 = 0.0f, rs1 = 0.0f;
#pragma unroll
        for (int nt = 0; nt < 8; nt++) {
            float p00 = __expf(s[nt][0] - mn0);
            float p01 = __expf(s[nt][1] - mn0);
            float p10 = __expf(s[nt][2] - mn1);
            float p11 = __expf(s[nt][3] - mn1);
            rs0 += p00 + p01;
            rs1 += p10 + p11;
            const int c = nt * 8 + 2 * lr;
            *(uint2*)&Ps[(w16 + lq) * PS_ST + c] =
                make_uint2(__float_as_uint(p00), __float_as_uint(p01));
            *(uint2*)&Ps[(w16 + lq + 8) * PS_ST + c] =
                make_uint2(__float_as_uint(p10), __float_as_uint(p11));
        }
        rs0 += __shfl_xor_sync(0xffffffffu, rs0, 1);
        rs0 += __shfl_xor_sync(0xffffffffu, rs0, 2);
        rs1 += __shfl_xor_sync(0xffffffffu, rs1, 1);
        rs1 += __shfl_xor_sync(0xffffffffu, rs1, 2);

        l0 = l0 * alpha0 + rs0;
        l1 = l1 * alpha1 + rs1;
        m0 = mn0;
        m1 = mn1;
#pragma unroll
        for (int nt = 0; nt < 8; nt++) {
            o[nt][0] *= alpha0; o[nt][1] *= alpha0;
            o[nt][2] *= alpha1; o[nt][3] *= alpha1;
        }
        __syncwarp();   // P rows are warp-private

        // ---- O += P V ----
#pragma unroll
        for (int kk8 = 0; kk8 < 8; kk8++) {
            const int c = kk8 * 8;
            uint32_t pa[4];
            pa[0] = Ps[(w16 + lq) * PS_ST + c + lr];
            pa[1] = Ps[(w16 + lq + 8) * PS_ST + c + lr];
            pa[2] = Ps[(w16 + lq) * PS_ST + c + lr + 4];
            pa[3] = Ps[(w16 + lq + 8) * PS_ST + c + lr + 4];
#pragma unroll
            for (int nt = 0; nt < 8; nt++) {
                const uint32_t b0 = Vst[(c + lr) * VS_ST + nt * 8 + lq];
                const uint32_t b1 = Vst[(c + lr + 4) * VS_ST + nt * 8 + lq];
                mma_tf32(o[nt][0], o[nt][1], o[nt][2], o[nt][3],
                         pa[0], pa[1], pa[2], pa[3], b0, b1);
            }
        }
        __syncthreads();
    }

    // ---- normalize + write ----
    const float inv0 = 1.0f / l0;
    const float inv1 = 1.0f / l1;
    const int r0 = q0 + w16 + lq;
    const int r1 = r0 + 8;
    const size_t base0 = ((size_t)(b * Tt + r0)) * Dd + h * HDd;
    const size_t base1 = ((size_t)(b * Tt + r1)) * Dd + h * HDd;
#pragma unroll
    for (int nt = 0; nt < 8; nt++) {
        const int c = nt * 8 + 2 * lr;
        *(float2*)&Ob[base0 + c] = make_float2(o[nt][0] * inv0, o[nt][1] * inv0);
        *(float2*)&Ob[base1 + c] = make_float2(o[nt][2] * inv1, o[nt][3] * inv1);
    }
}

// ---------------- residual add + LayerNorm ---------------------------------
__device__ __forceinline__ float block_sum_1024(float v, float* red) {
    const int tid = threadIdx.x;
    __syncthreads();
#pragma unroll
    for (int o = 16; o > 0; o >>= 1)
        v += __shfl_xor_sync(0xffffffffu, v, o);
    if ((tid & 31) == 0) red[tid >> 5] = v;
    __syncthreads();
    float t = (tid < 8) ? red[tid] : 0.0f;
    if (tid < 32) {
#pragma unroll
        for (int o = 4; o > 0; o >>= 1)
            t += __shfl_xor_sync(0xffffffffu, t, o);
        if (tid == 0) red[0] = t;
    }
    __syncthreads();
    return red[0];
}

__global__ __launch_bounds__(256) void add_ln_kernel(
    const float* __restrict__ A, const float* __restrict__ Bv,
    const float* __restrict__ g, const float* __restrict__ be,
    float* __restrict__ out)
{
    __shared__ float red[8];
    const int row = blockIdx.x;
    const int tid = threadIdx.x;
    const size_t base = (size_t)row * Dd;
    const int c = tid * 4;

    float4 a = *(const float4*)&A[base + c];
    float4 b = *(const float4*)&Bv[base + c];
    float v0 = a.x + b.x, v1 = a.y + b.y, v2 = a.z + b.z, v3 = a.w + b.w;

    float s = block_sum_1024(v0 + v1 + v2 + v3, red);
    const float mu = s * (1.0f / Dd);
    float d0 = v0 - mu, d1 = v1 - mu, d2 = v2 - mu, d3 = v3 - mu;
    float q = block_sum_1024(d0 * d0 + d1 * d1 + d2 * d2 + d3 * d3, red);
    const float inv = rsqrtf(q * (1.0f / Dd) + 1e-5f);

    float4 gv = *(const float4*)&g[c];
    float4 bev = *(const float4*)&be[c];
    float4 o;
    o.x = d0 * inv * gv.x + bev.x;
    o.y = d1 * inv * gv.y + bev.y;
    o.z = d2 * inv * gv.z + bev.z;
    o.w = d3 * inv * gv.w + bev.w;
    *(float4*)&out[base + c] = o;
}

// ---------------- orchestration --------------------------------------------
extern "C" void kernel_launch(void* const* d_in, const int* in_sizes, int n_in,
                              void* d_out, int out_size)
{
    const float* x   = (const float*)d_in[0];
    const float* wq  = (const float*)d_in[1];
    const float* wk  = (const float*)d_in[2];
    const float* wv  = (const float*)d_in[3];
    const float* wo  = (const float*)d_in[4];
    const float* w1  = (const float*)d_in[5];
    const float* b1  = (const float*)d_in[6];
    const float* w2  = (const float*)d_in[7];
    const float* b2  = (const float*)d_in[8];
    const float* g1  = (const float*)d_in[9];
    const float* be1 = (const float*)d_in[10];
    const float* g2  = (const float*)d_in[11];
    const float* be2 = (const float*)d_in[12];

    float *Q, *K, *V, *attn, *proj, *h, *ff1, *ff2;
    cudaGetSymbolAddress((void**)&Q,    g_Q);
    cudaGetSymbolAddress((void**)&K,    g_K);
    cudaGetSymbolAddress((void**)&V,    g_V);
    cudaGetSymbolAddress((void**)&attn, g_attn);
    cudaGetSymbolAddress((void**)&proj, g_proj);
    cudaGetSymbolAddress((void**)&h,    g_h);
    cudaGetSymbolAddress((void**)&ff1,  g_ff1);
    cudaGetSymbolAddress((void**)&ff2,  g_ff2);

    cudaFuncSetAttribute(gemm_cp_kernel<0>,
                         cudaFuncAttributeMaxDynamicSharedMemorySize, GEMM_SMEM);
    cudaFuncSetAttribute(gemm_cp_kernel<1>,
                         cudaFuncAttributeMaxDynamicSharedMemorySize, GEMM_SMEM);
    cudaFuncSetAttribute(gemm_cp_kernel<2>,
                         cudaFuncAttributeMaxDynamicSharedMemorySize, GEMM_SMEM);
    cudaFuncSetAttribute(flash_tc_kernel,
                         cudaFuncAttributeMaxDynamicSharedMemorySize, FLASH_SMEM);

    const dim3 blk(256);
    const dim3 gD (Dd  / 256, Mrows / 128);   // 4 x 64
    const dim3 gDF(DFf / 256, Mrows / 128);   // 16 x 64

    gemm_cp_kernel<0><<<gD, blk, GEMM_SMEM>>>(x, wq, nullptr, Q, Mrows, Dd, Dd);
    gemm_cp_kernel<0><<<gD, blk, GEMM_SMEM>>>(x, wk, nullptr, K, Mrows, Dd, Dd);
    gemm_cp_kernel<0><<<gD, blk, GEMM_SMEM>>>(x, wv, nullptr, V, Mrows, Dd, Dd);

    flash_tc_kernel<<<dim3(Tt / 128, Bb * Hh), blk, FLASH_SMEM>>>(Q, K, V, attn);

    gemm_cp_kernel<0><<<gD, blk, GEMM_SMEM>>>(attn, wo, nullptr, proj, Mrows, Dd, Dd);

    add_ln_kernel<<<Mrows, blk>>>(x, proj, g1, be1, h);

    gemm_cp_kernel<2><<<gDF, blk, GEMM_SMEM>>>(h, w1, b1, ff1, Mrows, DFf, Dd);
    gemm_cp_kernel<1><<<gD,  blk, GEMM_SMEM>>>(ff1, w2, b2, ff2, Mrows, Dd, DFf);

    add_ln_kernel<<<Mrows, blk>>>(h, ff2, g2, be2, (float*)d_out);
}

// round 10
// speedup vs baseline: 1.6036x; 1.6036x over previous
#include <cuda_runtime.h>
#include <cuda_fp16.h>
#include <math.h>
#include <stdint.h>

// Problem shape (fixed)
static constexpr int Bb = 4;
static constexpr int Tt = 2048;
static constexpr int Dd = 1024;
static constexpr int Hh = 16;
static constexpr int HDd = 64;
static constexpr int DFf = 4096;
static constexpr int Mrows = Bb * Tt;   // 8192

// ---------------- scratch (device globals; no allocation allowed) ----------
__device__ float g_Q[(size_t)Mrows * Dd];
__device__ float g_K[(size_t)Mrows * Dd];
__device__ float g_V[(size_t)Mrows * Dd];
__device__ float g_attn[(size_t)Mrows * Dd];
__device__ float g_proj[(size_t)Mrows * Dd];
__device__ float g_h[(size_t)Mrows * Dd];
__device__ float g_ff2[(size_t)Mrows * Dd];
// fp16 activations / weights
__device__ __half g_xh[(size_t)Mrows * Dd];
__device__ __half g_attnh[(size_t)Mrows * Dd];
__device__ __half g_hh[(size_t)Mrows * Dd];
__device__ __half g_ff1h[(size_t)Mrows * DFf];
__device__ __half g_wqh[(size_t)Dd * Dd];
__device__ __half g_wkh[(size_t)Dd * Dd];
__device__ __half g_wvh[(size_t)Dd * Dd];
__device__ __half g_woh[(size_t)Dd * Dd];
__device__ __half g_w1h[(size_t)Dd * DFf];
__device__ __half g_w2h[(size_t)DFf * Dd];

// ---------------- helpers ----------------
__device__ __forceinline__ float gelu_exact(float x) {
    return 0.5f * x * (1.0f + erff(x * 0.70710678118654752f));
}

__device__ __forceinline__ void cp_async16(uint32_t smem_addr, const void* gptr) {
    asm volatile("cp.async.cg.shared.global [%0], [%1], 16;\n"
                 :: "r"(smem_addr), "l"(gptr));
}
__device__ __forceinline__ void cp_commit() {
    asm volatile("cp.async.commit_group;\n");
}
template <int N>
__device__ __forceinline__ void cp_wait() {
    asm volatile("cp.async.wait_group %0;\n" :: "n"(N));
}

__device__ __forceinline__ uint32_t smem_u32(const void* p) {
    return (uint32_t)__cvta_generic_to_shared(p);
}

// fp16 tensor core mma: D(16x8,f32) += A(16x16,f16) * B(16x8,f16)
__device__ __forceinline__ void mma_f16(
    float& c0, float& c1, float& c2, float& c3,
    uint32_t a0, uint32_t a1, uint32_t a2, uint32_t a3,
    uint32_t b0, uint32_t b1)
{
    asm volatile(
        "mma.sync.aligned.m16n8k16.row.col.f32.f16.f16.f32 "
        "{%0,%1,%2,%3}, {%4,%5,%6,%7}, {%8,%9}, {%0,%1,%2,%3};\n"
        : "+f"(c0), "+f"(c1), "+f"(c2), "+f"(c3)
        : "r"(a0), "r"(a1), "r"(a2), "r"(a3), "r"(b0), "r"(b1));
}

// legacy tf32 mma (flash kernel)
__device__ __forceinline__ void mma_tf32(
    float& c0, float& c1, float& c2, float& c3,
    uint32_t a0, uint32_t a1, uint32_t a2, uint32_t a3,
    uint32_t b0, uint32_t b1)
{
    asm volatile(
        "mma.sync.aligned.m16n8k8.row.col.f32.tf32.tf32.f32 "
        "{%0,%1,%2,%3}, {%4,%5,%6,%7}, {%8,%9}, {%0,%1,%2,%3};\n"
        : "+f"(c0), "+f"(c1), "+f"(c2), "+f"(c3)
        : "r"(a0), "r"(a1), "r"(a2), "r"(a3), "r"(b0), "r"(b1));
}

__device__ __forceinline__ void ldsm_x4(
    uint32_t& r0, uint32_t& r1, uint32_t& r2, uint32_t& r3, uint32_t addr)
{
    asm volatile("ldmatrix.sync.aligned.m8n8.x4.shared.b16 {%0,%1,%2,%3}, [%4];"
                 : "=r"(r0), "=r"(r1), "=r"(r2), "=r"(r3) : "r"(addr));
}
__device__ __forceinline__ void ldsm_x4_t(
    uint32_t& r0, uint32_t& r1, uint32_t& r2, uint32_t& r3, uint32_t addr)
{
    asm volatile("ldmatrix.sync.aligned.m8n8.x4.trans.shared.b16 {%0,%1,%2,%3}, [%4];"
                 : "=r"(r0), "=r"(r1), "=r"(r2), "=r"(r3) : "r"(addr));
}

// ---------------- fp16 tensor-core GEMM, cp.async 4-stage -------------------
// C[M,N] = A[M,K] @ B[K,N] (+bias)(+gelu).
// Block 128x128, BK=32, 256 threads (8 warps), warp tile 64x32.
// A smem: [128 rows][40 halfs]  (80 B rows: 8-row ldmatrix covers all banks)
// B smem: [32 rows][128 halfs]  (256 B rows, 16B-chunk XOR swizzle c^=(k&7))
static constexpr int HAS_B = 80;                     // A row bytes
static constexpr int HA_BYTES = 128 * HAS_B;         // 10240
static constexpr int HB_BYTES = 32 * 256;            // 8192
static constexpr int HSTAGE = HA_BYTES + HB_BYTES;   // 18432
static constexpr int HSTAGES = 4;
static constexpr int HGEMM_SMEM = HSTAGES * HSTAGE;  // 73728 B

// OUTH: 0 = float out, 1 = half out.  EPI: 0 none, 1 +bias, 2 +bias+gelu
template <int OUTH, int EPI>
__global__ __launch_bounds__(256) void gemm_h_kernel(
    const __half* __restrict__ A, const __half* __restrict__ Bm,
    const float* __restrict__ bias, void* __restrict__ Cout,
    int M, int N, int K)
{
    extern __shared__ __align__(128) char smem[];
    const uint32_t sbase = smem_u32(smem);

    const int tid = threadIdx.x;
    const int warp = tid >> 5;
    const int lane = tid & 31;
    const int lq = lane >> 2;
    const int lr = lane & 3;

    const int bm = blockIdx.y * 128;
    const int bn = blockIdx.x * 128;
    const int wm = (warp & 1) * 64;
    const int wn = (warp >> 1) * 32;

    // A: 512 16B-chunks (128 rows x 4); 2 per thread
    const int a_r0 = tid >> 2;               // 0..63
    const int a_r1 = (tid + 256) >> 2;       // 64..127
    const int a_c  = tid & 3;                // chunk 0..3 (8 halfs each)
    // B: 512 chunks (32 rows x 16); 2 per thread
    const int b_k0 = tid >> 4;               // 0..15
    const int b_k1 = (tid + 256) >> 4;       // 16..31
    const int b_c  = tid & 15;

    const uint32_t sa0 = a_r0 * HAS_B + a_c * 16;
    const uint32_t sa1 = a_r1 * HAS_B + a_c * 16;
    const uint32_t sb0 = HA_BYTES + b_k0 * 256 + ((b_c ^ (b_k0 & 7)) * 16);
    const uint32_t sb1 = HA_BYTES + b_k1 * 256 + ((b_c ^ (b_k1 & 7)) * 16);

    const __half* Ag = A + (size_t)bm * K;
    const __half* Bg = Bm + bn;

    auto issue = [&](int kt, int stage) {
        const uint32_t st = sbase + stage * HSTAGE;
        const int k0 = kt * 32;
        cp_async16(st + sa0, Ag + (size_t)a_r0 * K + k0 + a_c * 8);
        cp_async16(st + sa1, Ag + (size_t)a_r1 * K + k0 + a_c * 8);
        cp_async16(st + sb0, Bg + (size_t)(k0 + b_k0) * N + b_c * 8);
        cp_async16(st + sb1, Bg + (size_t)(k0 + b_k1) * N + b_c * 8);
        cp_commit();
    };

    const int KT = K / 32;
#pragma unroll
    for (int s = 0; s < HSTAGES - 1; s++) issue(s, s);

    float acc[4][4][4];
#pragma unroll
    for (int i = 0; i < 4; i++)
#pragma unroll
        for (int j = 0; j < 4; j++)
#pragma unroll
            for (int r = 0; r < 4; r++) acc[i][j][r] = 0.0f;

    // ldmatrix lane-address components (byte offsets within stage)
    const int a_lrow = lane & 15;            // rows m..m+15
    const int a_lkof = (lane >> 4) * 16;     // k0 / k8 halves -> +16B
    const int b_lrow = lane & 15;            // rows k..k+15
    const int b_lnof = (lane >> 4) * 8;      // n-group 0 / +8

    for (int it = 0; it < KT; ++it) {
        cp_wait<HSTAGES - 2>();
        __syncthreads();
        if (it + HSTAGES - 1 < KT) issue(it + HSTAGES - 1, (it + HSTAGES - 1) & 3);

        const uint32_t Asb = sbase + (it & 3) * HSTAGE;
        const uint32_t Bsb = Asb + HA_BYTES;

#pragma unroll
        for (int kk = 0; kk < 32; kk += 16) {
            uint32_t af[4][4];
#pragma unroll
            for (int mt = 0; mt < 4; mt++) {
                const int row = wm + mt * 16 + a_lrow;
                ldsm_x4(af[mt][0], af[mt][1], af[mt][2], af[mt][3],
                        Asb + row * HAS_B + kk * 2 + a_lkof);
            }
            uint32_t bf[4][2];
#pragma unroll
            for (int pr = 0; pr < 2; pr++) {
                const int r = kk + b_lrow;
                const int n0 = wn + pr * 16 + b_lnof;
                const uint32_t addr =
                    Bsb + r * 256 + (((n0 >> 3) ^ (r & 7)) * 16);
                ldsm_x4_t(bf[pr * 2][0], bf[pr * 2][1],
                          bf[pr * 2 + 1][0], bf[pr * 2 + 1][1], addr);
            }
#pragma unroll
            for (int mt = 0; mt < 4; mt++)
#pragma unroll
                for (int nt = 0; nt < 4; nt++)
                    mma_f16(acc[mt][nt][0], acc[mt][nt][1],
                            acc[mt][nt][2], acc[mt][nt][3],
                            af[mt][0], af[mt][1], af[mt][2], af[mt][3],
                            bf[nt][0], bf[nt][1]);
        }
        __syncthreads();
    }

    // ---- epilogue: c0,c1 = (row lq, cols 2lr,2lr+1); c2,c3 = row lq+8 ----
#pragma unroll
    for (int mt = 0; mt < 4; mt++) {
#pragma unroll
        for (int nt = 0; nt < 4; nt++) {
            const int col = bn + wn + nt * 8 + 2 * lr;
#pragma unroll
            for (int half_i = 0; half_i < 2; half_i++) {
                const int row = bm + wm + mt * 16 + lq + half_i * 8;
                float v0 = acc[mt][nt][half_i * 2 + 0];
                float v1 = acc[mt][nt][half_i * 2 + 1];
                if (EPI >= 1) {
                    v0 += bias[col];
                    v1 += bias[col + 1];
                }
                if (EPI == 2) {
                    v0 = gelu_exact(v0);
                    v1 = gelu_exact(v1);
                }
                if (OUTH) {
                    __half2 hv = __floats2half2_rn(v0, v1);
                    *(__half2*)((__half*)Cout + (size_t)row * N + col) = hv;
                } else {
                    *(float2*)((float*)Cout + (size_t)row * N + col) =
                        make_float2(v0, v1);
                }
            }
        }
    }
}

// ---------------- fp32 -> fp16 convert --------------------------------------
__global__ __launch_bounds__(256) void cvt_h_kernel(
    const float* __restrict__ in, __half* __restrict__ out)
{
    const size_t i = ((size_t)blockIdx.x * 256 + threadIdx.x) * 4;
    float4 v = *(const float4*)&in[i];
    __half2 h0 = __floats2half2_rn(v.x, v.y);
    __half2 h1 = __floats2half2_rn(v.z, v.w);
    *(__half2*)&out[i] = h0;
    *(__half2*)&out[i + 2] = h1;
}

// ---------------- tensor-core flash attention (unchanged, fp32/tf32) --------
static constexpr int KS_ST = 68;
static constexpr int VS_ST = 72;
static constexpr int PS_ST = 68;
static constexpr int KBUF = 64 * KS_ST;
static constexpr int VBUF = 64 * VS_ST;
static constexpr int FLASH_SMEM = (2 * KBUF + 2 * VBUF + 128 * PS_ST) * 4;

__global__ __launch_bounds__(256) void flash_tc_kernel(
    const float* __restrict__ Qb, const float* __restrict__ Kb,
    const float* __restrict__ Vb, float* __restrict__ Ob)
{
    extern __shared__ uint32_t smu[];
    uint32_t* Ks[2] = { smu, smu + KBUF };
    uint32_t* Vs[2] = { smu + 2 * KBUF, smu + 2 * KBUF + VBUF };
    uint32_t* Ps = smu + 2 * KBUF + 2 * VBUF;
    float*    Psf = (float*)Ps;
    const uint32_t sbase = smem_u32(smu);

    const int tid = threadIdx.x;
    const int warp = tid >> 5;
    const int lane = tid & 31;
    const int lq = lane >> 2;
    const int lr = lane & 3;

    const int b = blockIdx.y / Hh;
    const int h = blockIdx.y % Hh;
    const int q0 = blockIdx.x * 128;
    const int w16 = warp * 16;

    const float scale = 0.125f;

    int kv_r[4], kv_c4[4];
#pragma unroll
    for (int it = 0; it < 4; it++) {
        const int id = tid + it * 256;
        kv_r[it] = id >> 4;
        kv_c4[it] = (id & 15) << 2;
    }

    auto issue_kv = [&](int kv_tile, int buf) {
        const size_t baseKV = ((size_t)(b * Tt + kv_tile * 64)) * Dd + h * HDd;
        const uint32_t kst = sbase + (uint32_t)(buf * KBUF * 4);
        const uint32_t vst = sbase + (uint32_t)((2 * KBUF + buf * VBUF) * 4);
#pragma unroll
        for (int it = 0; it < 4; it++) {
            const size_t g = baseKV + (size_t)kv_r[it] * Dd + kv_c4[it];
            cp_async16(kst + (kv_r[it] * KS_ST + kv_c4[it]) * 4, Kb + g);
            cp_async16(vst + (kv_r[it] * VS_ST + kv_c4[it]) * 4, Vb + g);
        }
    };

    issue_kv(0, 0);
    cp_commit();

    {
        const size_t baseQ = ((size_t)(b * Tt + q0)) * Dd + h * HDd;
#pragma unroll
        for (int it = 0; it < 8; it++) {
            const int id = tid + it * 256;
            const int r = id >> 4, c4 = (id & 15) << 2;
            float4 v = *(const float4*)&Qb[baseQ + (size_t)r * Dd + c4];
            float* p = &Psf[r * PS_ST + c4];
            p[0] = v.x; p[1] = v.y; p[2] = v.z; p[3] = v.w;
        }
    }
    __syncthreads();

    uint32_t qa[8][4];
#pragma unroll
    for (int kk8 = 0; kk8 < 8; kk8++) {
        const int c = kk8 * 8;
        qa[kk8][0] = __float_as_uint(Psf[(w16 + lq) * PS_ST + c + lr] * scale);
        qa[kk8][1] = __float_as_uint(Psf[(w16 + lq + 8) * PS_ST + c + lr] * scale);
        qa[kk8][2] = __float_as_uint(Psf[(w16 + lq) * PS_ST + c + lr + 4] * scale);
        qa[kk8][3] = __float_as_uint(Psf[(w16 + lq + 8) * PS_ST + c + lr + 4] * scale);
    }
    __syncthreads();

    float o[8][4];
#pragma unroll
    for (int nt = 0; nt < 8; nt++)
#pragma unroll
        for (int r = 0; r < 4; r++) o[nt][r] = 0.0f;
    float m0 = -INFINITY, m1 = -INFINITY;
    float l0 = 0.0f, l1 = 0.0f;

    const int NT = Tt / 64;
    for (int t = 0; t < NT; ++t) {
        if (t + 1 < NT) issue_kv(t + 1, (t + 1) & 1);
        cp_commit();
        cp_wait<1>();
        __syncthreads();

        const uint32_t* Kst = Ks[t & 1];
        const uint32_t* Vst = Vs[t & 1];

        float s[8][4];
#pragma unroll
        for (int nt = 0; nt < 8; nt++)
#pragma unroll
            for (int r = 0; r < 4; r++) s[nt][r] = 0.0f;

#pragma unroll
        for (int kk8 = 0; kk8 < 8; kk8++) {
            const int c = kk8 * 8;
#pragma unroll
            for (int nt = 0; nt < 8; nt++) {
                const uint32_t b0 = Kst[(nt * 8 + lq) * KS_ST + c + lr];
                const uint32_t b1 = Kst[(nt * 8 + lq) * KS_ST + c + lr + 4];
                mma_tf32(s[nt][0], s[nt][1], s[nt][2], s[nt][3],
                         qa[kk8][0], qa[kk8][1], qa[kk8][2], qa[kk8][3],
                         b0, b1);
            }
        }

        float rm0 = -INFINITY, rm1 = -INFINITY;
#pragma unroll
        for (int nt = 0; nt < 8; nt++) {
            rm0 = fmaxf(rm0, fmaxf(s[nt][0], s[nt][1]));
            rm1 = fmaxf(rm1, fmaxf(s[nt][2], s[nt][3]));
        }
        rm0 = fmaxf(rm0, __shfl_xor_sync(0xffffffffu, rm0, 1));
        rm0 = fmaxf(rm0, __shfl_xor_sync(0xffffffffu, rm0, 2));
        rm1 = fmaxf(rm1, __shfl_xor_sync(0xffffffffu, rm1, 1));
        rm1 = fmaxf(rm1, __shfl_xor_sync(0xffffffffu, rm1, 2));
        const float mn0 = fmaxf(m0, rm0);
        const float mn1 = fmaxf(m1, rm1);
        const float alpha0 = __expf(m0 - mn0);
        const float alpha1 = __expf(m1 - mn1);

        float rs0 = 0.0f, rs1 = 0.0f;
#pragma unroll
        for (int nt = 0; nt < 8; nt++) {
            float p00 = __expf(s[nt][0] - mn0);
            float p01 = __expf(s[nt][1] - mn0);
            float p10 = __expf(s[nt][2] - mn1);
            float p11 = __expf(s[nt][3] - mn1);
            rs0 += p00 + p01;
            rs1 += p10 + p11;
            const int c = nt * 8 + 2 * lr;
            *(uint2*)&Ps[(w16 + lq) * PS_ST + c] =
                make_uint2(__float_as_uint(p00), __float_as_uint(p01));
            *(uint2*)&Ps[(w16 + lq + 8) * PS_ST + c] =
                make_uint2(__float_as_uint(p10), __float_as_uint(p11));
        }
        rs0 += __shfl_xor_sync(0xffffffffu, rs0, 1);
        rs0 += __shfl_xor_sync(0xffffffffu, rs0, 2);
        rs1 += __shfl_xor_sync(0xffffffffu, rs1, 1);
        rs1 += __shfl_xor_sync(0xffffffffu, rs1, 2);

        l0 = l0 * alpha0 + rs0;
        l1 = l1 * alpha1 + rs1;
        m0 = mn0;
        m1 = mn1;
#pragma unroll
        for (int nt = 0; nt < 8; nt++) {
            o[nt][0] *= alpha0; o[nt][1] *= alpha0;
            o[nt][2] *= alpha1; o[nt][3] *= alpha1;
        }
        __syncwarp();

#pragma unroll
        for (int kk8 = 0; kk8 < 8; kk8++) {
            const int c = kk8 * 8;
            uint32_t pa[4];
            pa[0] = Ps[(w16 + lq) * PS_ST + c + lr];
            pa[1] = Ps[(w16 + lq + 8) * PS_ST + c + lr];
            pa[2] = Ps[(w16 + lq) * PS_ST + c + lr + 4];
            pa[3] = Ps[(w16 + lq + 8) * PS_ST + c + lr + 4];
#pragma unroll
            for (int nt = 0; nt < 8; nt++) {
                const uint32_t b0 = Vst[(c + lr) * VS_ST + nt * 8 + lq];
                const uint32_t b1 = Vst[(c + lr + 4) * VS_ST + nt * 8 + lq];
                mma_tf32(o[nt][0], o[nt][1], o[nt][2], o[nt][3],
                         pa[0], pa[1], pa[2], pa[3], b0, b1);
            }
        }
        __syncthreads();
    }

    const float inv0 = 1.0f / l0;
    const float inv1 = 1.0f / l1;
    const int r0 = q0 + w16 + lq;
    const int r1 = r0 + 8;
    const size_t base0 = ((size_t)(b * Tt + r0)) * Dd + h * HDd;
    const size_t base1 = ((size_t)(b * Tt + r1)) * Dd + h * HDd;
#pragma unroll
    for (int nt = 0; nt < 8; nt++) {
        const int c = nt * 8 + 2 * lr;
        *(float2*)&Ob[base0 + c] = make_float2(o[nt][0] * inv0, o[nt][1] * inv0);
        *(float2*)&Ob[base1 + c] = make_float2(o[nt][2] * inv1, o[nt][3] * inv1);
    }
}

// ---------------- residual add + LayerNorm ---------------------------------
__device__ __forceinline__ float block_sum_1024(float v, float* red) {
    const int tid = threadIdx.x;
    __syncthreads();
#pragma unroll
    for (int o = 16; o > 0; o >>= 1)
        v += __shfl_xor_sync(0xffffffffu, v, o);
    if ((tid & 31) == 0) red[tid >> 5] = v;
    __syncthreads();
    float t = (tid < 8) ? red[tid] : 0.0f;
    if (tid < 32) {
#pragma unroll
        for (int o = 4; o > 0; o >>= 1)
            t += __shfl_xor_sync(0xffffffffu, t, o);
        if (tid == 0) red[0] = t;
    }
    __syncthreads();
    return red[0];
}

// Writes fp32 `out`; optionally also fp16 `outh` (for downstream GEMM A input)
__global__ __launch_bounds__(256) void add_ln_kernel(
    const float* __restrict__ A, const float* __restrict__ Bv,
    const float* __restrict__ g, const float* __restrict__ be,
    float* __restrict__ out, __half* __restrict__ outh)
{
    __shared__ float red[8];
    const int row = blockIdx.x;
    const int tid = threadIdx.x;
    const size_t base = (size_t)row * Dd;
    const int c = tid * 4;

    float4 a = *(const float4*)&A[base + c];
    float4 b = *(const float4*)&Bv[base + c];
    float v0 = a.x + b.x, v1 = a.y + b.y, v2 = a.z + b.z, v3 = a.w + b.w;

    float s = block_sum_1024(v0 + v1 + v2 + v3, red);
    const float mu = s * (1.0f / Dd);
    float d0 = v0 - mu, d1 = v1 - mu, d2 = v2 - mu, d3 = v3 - mu;
    float q = block_sum_1024(d0 * d0 + d1 * d1 + d2 * d2 + d3 * d3, red);
    const float inv = rsqrtf(q * (1.0f / Dd) + 1e-5f);

    float4 gv = *(const float4*)&g[c];
    float4 bev = *(const float4*)&be[c];
    float4 o;
    o.x = d0 * inv * gv.x + bev.x;
    o.y = d1 * inv * gv.y + bev.y;
    o.z = d2 * inv * gv.z + bev.z;
    o.w = d3 * inv * gv.w + bev.w;
    *(float4*)&out[base + c] = o;
    if (outh != nullptr) {
        *(__half2*)&outh[base + c]     = __floats2half2_rn(o.x, o.y);
        *(__half2*)&outh[base + c + 2] = __floats2half2_rn(o.z, o.w);
    }
}

// ---------------- orchestration --------------------------------------------
extern "C" void kernel_launch(void* const* d_in, const int* in_sizes, int n_in,
                              void* d_out, int out_size)
{
    const float* x   = (const float*)d_in[0];
    const float* wq  = (const float*)d_in[1];
    const float* wk  = (const float*)d_in[2];
    const float* wv  = (const float*)d_in[3];
    const float* wo  = (const float*)d_in[4];
    const float* w1  = (const float*)d_in[5];
    const float* b1  = (const float*)d_in[6];
    const float* w2  = (const float*)d_in[7];
    const float* b2  = (const float*)d_in[8];
    const float* g1  = (const float*)d_in[9];
    const float* be1 = (const float*)d_in[10];
    const float* g2  = (const float*)d_in[11];
    const float* be2 = (const float*)d_in[12];

    float *Q, *K, *V, *attn, *proj, *h, *ff2;
    __half *xh, *attnh, *hh, *ff1h, *wqh, *wkh, *wvh, *woh, *w1h, *w2h;
    cudaGetSymbolAddress((void**)&Q,     g_Q);
    cudaGetSymbolAddress((void**)&K,     g_K);
    cudaGetSymbolAddress((void**)&V,     g_V);
    cudaGetSymbolAddress((void**)&attn,  g_attn);
    cudaGetSymbolAddress((void**)&proj,  g_proj);
    cudaGetSymbolAddress((void**)&h,     g_h);
    cudaGetSymbolAddress((void**)&ff2,   g_ff2);
    cudaGetSymbolAddress((void**)&xh,    g_xh);
    cudaGetSymbolAddress((void**)&attnh, g_attnh);
    cudaGetSymbolAddress((void**)&hh,    g_hh);
    cudaGetSymbolAddress((void**)&ff1h,  g_ff1h);
    cudaGetSymbolAddress((void**)&wqh,   g_wqh);
    cudaGetSymbolAddress((void**)&wkh,   g_wkh);
    cudaGetSymbolAddress((void**)&wvh,   g_wvh);
    cudaGetSymbolAddress((void**)&woh,   g_woh);
    cudaGetSymbolAddress((void**)&w1h,   g_w1h);
    cudaGetSymbolAddress((void**)&w2h,   g_w2h);

    cudaFuncSetAttribute(gemm_h_kernel<0, 0>,
                         cudaFuncAttributeMaxDynamicSharedMemorySize, HGEMM_SMEM);
    cudaFuncSetAttribute(gemm_h_kernel<1, 2>,
                         cudaFuncAttributeMaxDynamicSharedMemorySize, HGEMM_SMEM);
    cudaFuncSetAttribute(gemm_h_kernel<0, 1>,
                         cudaFuncAttributeMaxDynamicSharedMemorySize, HGEMM_SMEM);
    cudaFuncSetAttribute(flash_tc_kernel,
                         cudaFuncAttributeMaxDynamicSharedMemorySize, FLASH_SMEM);

    // fp16 conversions (elementwise, float4 per thread)
    auto cvt = [](const float* in, __half* out, size_t n) {
        cvt_h_kernel<<<(unsigned)(n / 1024), 256>>>(in, out);
    };
    cvt(x,  xh,  (size_t)Mrows * Dd);
    cvt(wq, wqh, (size_t)Dd * Dd);
    cvt(wk, wkh, (size_t)Dd * Dd);
    cvt(wv, wvh, (size_t)Dd * Dd);
    cvt(wo, woh, (size_t)Dd * Dd);
    cvt(w1, w1h, (size_t)Dd * DFf);
    cvt(w2, w2h, (size_t)DFf * Dd);

    const dim3 gblk(256);
    const dim3 gD (Dd  / 128, Mrows / 128);   // (8, 64)
    const dim3 gDF(DFf / 128, Mrows / 128);   // (32, 64)

    gemm_h_kernel<0, 0><<<gD, gblk, HGEMM_SMEM>>>(xh, wqh, nullptr, Q, Mrows, Dd, Dd);
    gemm_h_kernel<0, 0><<<gD, gblk, HGEMM_SMEM>>>(xh, wkh, nullptr, K, Mrows, Dd, Dd);
    gemm_h_kernel<0, 0><<<gD, gblk, HGEMM_SMEM>>>(xh, wvh, nullptr, V, Mrows, Dd, Dd);

    flash_tc_kernel<<<dim3(Tt / 128, Bb * Hh), dim3(256), FLASH_SMEM>>>(Q, K, V, attn);

    cvt(attn, attnh, (size_t)Mrows * Dd);
    gemm_h_kernel<0, 0><<<gD, gblk, HGEMM_SMEM>>>(attnh, woh, nullptr, proj, Mrows, Dd, Dd);

    add_ln_kernel<<<Mrows, 256>>>(x, proj, g1, be1, h, hh);

    gemm_h_kernel<1, 2><<<gDF, gblk, HGEMM_SMEM>>>(hh, w1h, b1, ff1h, Mrows, DFf, Dd);
    gemm_h_kernel<0, 1><<<gD,  gblk, HGEMM_SMEM>>>(ff1h, w2h, b2, ff2, Mrows, Dd, DFf);

    add_ln_kernel<<<Mrows, 256>>>(h, ff2, g2, be2, (float*)d_out, nullptr);
}

// round 11
// speedup vs baseline: 2.2228x; 1.3861x over previous
#include <cuda_runtime.h>
#include <cuda_fp16.h>
#include <math.h>
#include <stdint.h>

// Problem shape (fixed)
static constexpr int Bb = 4;
static constexpr int Tt = 2048;
static constexpr int Dd = 1024;
static constexpr int Hh = 16;
static constexpr int HDd = 64;
static constexpr int DFf = 4096;
static constexpr int Mrows = Bb * Tt;   // 8192

// ---------------- scratch (device globals; no allocation allowed) ----------
__device__ float g_proj[(size_t)Mrows * Dd];
__device__ float g_h[(size_t)Mrows * Dd];
__device__ float g_ff2[(size_t)Mrows * Dd];
// fp16 activations / weights
__device__ __half g_xh[(size_t)Mrows * Dd];
__device__ __half g_Qh[(size_t)Mrows * Dd];
__device__ __half g_Kh[(size_t)Mrows * Dd];
__device__ __half g_Vh[(size_t)Mrows * Dd];
__device__ __half g_attnh[(size_t)Mrows * Dd];
__device__ __half g_hh[(size_t)Mrows * Dd];
__device__ __half g_ff1h[(size_t)Mrows * DFf];
__device__ __half g_wqh[(size_t)Dd * Dd];
__device__ __half g_wkh[(size_t)Dd * Dd];
__device__ __half g_wvh[(size_t)Dd * Dd];
__device__ __half g_woh[(size_t)Dd * Dd];
__device__ __half g_w1h[(size_t)Dd * DFf];
__device__ __half g_w2h[(size_t)DFf * Dd];

// ---------------- helpers ----------------
__device__ __forceinline__ float gelu_exact(float x) {
    return 0.5f * x * (1.0f + erff(x * 0.70710678118654752f));
}

__device__ __forceinline__ void cp_async16(uint32_t smem_addr, const void* gptr) {
    asm volatile("cp.async.cg.shared.global [%0], [%1], 16;\n"
                 :: "r"(smem_addr), "l"(gptr));
}
__device__ __forceinline__ void cp_commit() {
    asm volatile("cp.async.commit_group;\n");
}
template <int N>
__device__ __forceinline__ void cp_wait() {
    asm volatile("cp.async.wait_group %0;\n" :: "n"(N));
}

__device__ __forceinline__ uint32_t smem_u32(const void* p) {
    return (uint32_t)__cvta_generic_to_shared(p);
}

// fp16 tensor core mma: D(16x8,f32) += A(16x16,f16) * B(16x8,f16)
__device__ __forceinline__ void mma_f16(
    float& c0, float& c1, float& c2, float& c3,
    uint32_t a0, uint32_t a1, uint32_t a2, uint32_t a3,
    uint32_t b0, uint32_t b1)
{
    asm volatile(
        "mma.sync.aligned.m16n8k16.row.col.f32.f16.f16.f32 "
        "{%0,%1,%2,%3}, {%4,%5,%6,%7}, {%8,%9}, {%0,%1,%2,%3};\n"
        : "+f"(c0), "+f"(c1), "+f"(c2), "+f"(c3)
        : "r"(a0), "r"(a1), "r"(a2), "r"(a3), "r"(b0), "r"(b1));
}

__device__ __forceinline__ void ldsm_x4(
    uint32_t& r0, uint32_t& r1, uint32_t& r2, uint32_t& r3, uint32_t addr)
{
    asm volatile("ldmatrix.sync.aligned.m8n8.x4.shared.b16 {%0,%1,%2,%3}, [%4];"
                 : "=r"(r0), "=r"(r1), "=r"(r2), "=r"(r3) : "r"(addr));
}
__device__ __forceinline__ void ldsm_x4_t(
    uint32_t& r0, uint32_t& r1, uint32_t& r2, uint32_t& r3, uint32_t addr)
{
    asm volatile("ldmatrix.sync.aligned.m8n8.x4.trans.shared.b16 {%0,%1,%2,%3}, [%4];"
                 : "=r"(r0), "=r"(r1), "=r"(r2), "=r"(r3) : "r"(addr));
}

__device__ __forceinline__ uint32_t pack_h2(float a, float b) {
    __half2 h = __floats2half2_rn(a, b);
    return *(uint32_t*)&h;
}

// ---------------- fp16 tensor-core GEMM, cp.async 4-stage -------------------
// C[M,N] = A[M,K] @ B[K,N] (+bias)(+gelu).
// Block 128x128, BK=32, 256 threads (8 warps), warp tile 64x32.
static constexpr int HAS_B = 80;                     // A row bytes
static constexpr int HA_BYTES = 128 * HAS_B;         // 10240
static constexpr int HB_BYTES = 32 * 256;            // 8192
static constexpr int HSTAGE = HA_BYTES + HB_BYTES;   // 18432
static constexpr int HSTAGES = 4;
static constexpr int HGEMM_SMEM = HSTAGES * HSTAGE;  // 73728 B

// OUTH: 0 = float out, 1 = half out.  EPI: 0 none, 1 +bias, 2 +bias+gelu
template <int OUTH, int EPI>
__global__ __launch_bounds__(256) void gemm_h_kernel(
    const __half* __restrict__ A, const __half* __restrict__ Bm,
    const float* __restrict__ bias, void* __restrict__ Cout,
    int M, int N, int K)
{
    extern __shared__ __align__(128) char smem[];
    const uint32_t sbase = smem_u32(smem);

    const int tid = threadIdx.x;
    const int warp = tid >> 5;
    const int lane = tid & 31;
    const int lq = lane >> 2;
    const int lr = lane & 3;

    const int bm = blockIdx.y * 128;
    const int bn = blockIdx.x * 128;
    const int wm = (warp & 1) * 64;
    const int wn = (warp >> 1) * 32;

    const int a_r0 = tid >> 2;
    const int a_r1 = (tid + 256) >> 2;
    const int a_c  = tid & 3;
    const int b_k0 = tid >> 4;
    const int b_k1 = (tid + 256) >> 4;
    const int b_c  = tid & 15;

    const uint32_t sa0 = a_r0 * HAS_B + a_c * 16;
    const uint32_t sa1 = a_r1 * HAS_B + a_c * 16;
    const uint32_t sb0 = HA_BYTES + b_k0 * 256 + ((b_c ^ (b_k0 & 7)) * 16);
    const uint32_t sb1 = HA_BYTES + b_k1 * 256 + ((b_c ^ (b_k1 & 7)) * 16);

    const __half* Ag = A + (size_t)bm * K;
    const __half* Bg = Bm + bn;

    auto issue = [&](int kt, int stage) {
        const uint32_t st = sbase + stage * HSTAGE;
        const int k0 = kt * 32;
        cp_async16(st + sa0, Ag + (size_t)a_r0 * K + k0 + a_c * 8);
        cp_async16(st + sa1, Ag + (size_t)a_r1 * K + k0 + a_c * 8);
        cp_async16(st + sb0, Bg + (size_t)(k0 + b_k0) * N + b_c * 8);
        cp_async16(st + sb1, Bg + (size_t)(k0 + b_k1) * N + b_c * 8);
        cp_commit();
    };

    const int KT = K / 32;
#pragma unroll
    for (int s = 0; s < HSTAGES - 1; s++) issue(s, s);

    float acc[4][4][4];
#pragma unroll
    for (int i = 0; i < 4; i++)
#pragma unroll
        for (int j = 0; j < 4; j++)
#pragma unroll
            for (int r = 0; r < 4; r++) acc[i][j][r] = 0.0f;

    const int a_lrow = lane & 15;
    const int a_lkof = (lane >> 4) * 16;
    const int b_lrow = lane & 15;
    const int b_lnof = (lane >> 4) * 8;

    for (int it = 0; it < KT; ++it) {
        cp_wait<HSTAGES - 2>();
        __syncthreads();
        if (it + HSTAGES - 1 < KT) issue(it + HSTAGES - 1, (it + HSTAGES - 1) & 3);

        const uint32_t Asb = sbase + (it & 3) * HSTAGE;
        const uint32_t Bsb = Asb + HA_BYTES;

#pragma unroll
        for (int kk = 0; kk < 32; kk += 16) {
            uint32_t af[4][4];
#pragma unroll
            for (int mt = 0; mt < 4; mt++) {
                const int row = wm + mt * 16 + a_lrow;
                ldsm_x4(af[mt][0], af[mt][1], af[mt][2], af[mt][3],
                        Asb + row * HAS_B + kk * 2 + a_lkof);
            }
            uint32_t bf[4][2];
#pragma unroll
            for (int pr = 0; pr < 2; pr++) {
                const int r = kk + b_lrow;
                const int n0 = wn + pr * 16 + b_lnof;
                const uint32_t addr =
                    Bsb + r * 256 + (((n0 >> 3) ^ (r & 7)) * 16);
                ldsm_x4_t(bf[pr * 2][0], bf[pr * 2][1],
                          bf[pr * 2 + 1][0], bf[pr * 2 + 1][1], addr);
            }
#pragma unroll
            for (int mt = 0; mt < 4; mt++)
#pragma unroll
                for (int nt = 0; nt < 4; nt++)
                    mma_f16(acc[mt][nt][0], acc[mt][nt][1],
                            acc[mt][nt][2], acc[mt][nt][3],
                            af[mt][0], af[mt][1], af[mt][2], af[mt][3],
                            bf[nt][0], bf[nt][1]);
        }
        __syncthreads();
    }

#pragma unroll
    for (int mt = 0; mt < 4; mt++) {
#pragma unroll
        for (int nt = 0; nt < 4; nt++) {
            const int col = bn + wn + nt * 8 + 2 * lr;
#pragma unroll
            for (int half_i = 0; half_i < 2; half_i++) {
                const int row = bm + wm + mt * 16 + lq + half_i * 8;
                float v0 = acc[mt][nt][half_i * 2 + 0];
                float v1 = acc[mt][nt][half_i * 2 + 1];
                if (EPI >= 1) {
                    v0 += bias[col];
                    v1 += bias[col + 1];
                }
                if (EPI == 2) {
                    v0 = gelu_exact(v0);
                    v1 = gelu_exact(v1);
                }
                if (OUTH) {
                    __half2 hv = __floats2half2_rn(v0, v1);
                    *(__half2*)((__half*)Cout + (size_t)row * N + col) = hv;
                } else {
                    *(float2*)((float*)Cout + (size_t)row * N + col) =
                        make_float2(v0, v1);
                }
            }
        }
    }
}

// ---------------- fp32 -> fp16 convert --------------------------------------
__global__ __launch_bounds__(256) void cvt_h_kernel(
    const float* __restrict__ in, __half* __restrict__ out)
{
    const size_t i = ((size_t)blockIdx.x * 256 + threadIdx.x) * 4;
    float4 v = *(const float4*)&in[i];
    *(__half2*)&out[i]     = __floats2half2_rn(v.x, v.y);
    *(__half2*)&out[i + 2] = __floats2half2_rn(v.z, v.w);
}

// ---------------- fp16 flash attention --------------------------------------
// Block: 128 q-rows x one (b,h); 8 warps, warp owns 16 q-rows; KV tile 64.
// All tiles stored as 128B rows (64 halfs) with 16B-chunk XOR swizzle
// chunk ^= (row & 7).  S = Q K^T uses K rows directly as B operand
// (non-trans ldmatrix); P V uses trans ldmatrix on V.  P stays in registers
// (S C-fragments map exactly onto A-fragments of the PV mma).
static constexpr int FQ_OFF = 0;                 // 128 rows * 128 B = 16 KB
static constexpr int FK_OFF = 16384;             // 2 x 8 KB
static constexpr int FV_OFF = 32768;             // 2 x 8 KB
static constexpr int FH_SMEM = 49152;

__global__ __launch_bounds__(256) void flash_h_kernel(
    const __half* __restrict__ Qb, const __half* __restrict__ Kb,
    const __half* __restrict__ Vb, __half* __restrict__ Ob)
{
    extern __shared__ __align__(128) char fsm[];
    const uint32_t sbase = smem_u32(fsm);

    const int tid = threadIdx.x;
    const int warp = tid >> 5;
    const int lane = tid & 31;
    const int lq = lane >> 2;
    const int lr = lane & 3;

    const int b = blockIdx.y / Hh;
    const int h = blockIdx.y % Hh;
    const int q0 = blockIdx.x * 128;
    const int w16 = warp * 16;

    // KV cp.async geometry: K tile = 64 rows x 8 chunks = 512; 2/thread
    int kv_r[2], kv_c[2];
#pragma unroll
    for (int it = 0; it < 2; it++) {
        const int id = tid + it * 256;
        kv_r[it] = id >> 3;
        kv_c[it] = id & 7;
    }

    auto issue_kv = [&](int tile, int buf) {
        const size_t baseKV = ((size_t)(b * Tt + tile * 64)) * Dd + h * HDd;
        const uint32_t kst = sbase + FK_OFF + buf * 8192;
        const uint32_t vst = sbase + FV_OFF + buf * 8192;
#pragma unroll
        for (int it = 0; it < 2; it++) {
            const int r = kv_r[it], c = kv_c[it];
            const size_t g = baseKV + (size_t)r * Dd + c * 8;
            const uint32_t so = r * 128 + ((c ^ (r & 7)) * 16);
            cp_async16(kst + so, Kb + g);
            cp_async16(vst + so, Vb + g);
        }
        cp_commit();
    };

    issue_kv(0, 0);

    // ---- stage Q tile [128 x 64] (swizzled) ----
    {
        const size_t baseQ = ((size_t)(b * Tt + q0)) * Dd + h * HDd;
#pragma unroll
        for (int it = 0; it < 4; it++) {
            const int id = tid + it * 256;
            const int r = id >> 3, c = id & 7;
            uint4 v = *(const uint4*)&Qb[baseQ + (size_t)r * Dd + c * 8];
            *(uint4*)(fsm + FQ_OFF + r * 128 + ((c ^ (r & 7)) * 16)) = v;
        }
    }
    __syncthreads();

    // ---- Q fragments (scaled by 1/8) in registers for whole block ----
    uint32_t qa[4][4];
    {
        const int arow = w16 + (lane & 15);
        const __half2 sc2 = __float2half2_rn(0.125f);
#pragma unroll
        for (int kc = 0; kc < 4; kc++) {
            const int chunk = kc * 2 + (lane >> 4);
            const uint32_t addr =
                sbase + FQ_OFF + arow * 128 + ((chunk ^ (arow & 7)) * 16);
            ldsm_x4(qa[kc][0], qa[kc][1], qa[kc][2], qa[kc][3], addr);
#pragma unroll
            for (int r = 0; r < 4; r++) {
                __half2 t = *(__half2*)&qa[kc][r];
                t = __hmul2(t, sc2);
                qa[kc][r] = *(uint32_t*)&t;
            }
        }
    }

    float o[8][4];
#pragma unroll
    for (int nt = 0; nt < 8; nt++)
#pragma unroll
        for (int r = 0; r < 4; r++) o[nt][r] = 0.0f;
    float m0 = -INFINITY, m1 = -INFINITY;
    float l0 = 0.0f, l1 = 0.0f;

    const int kv_group = lane >> 3;     // 0..3
    const int kv_within = lane & 7;

    const int NT = Tt / 64;   // 32
    for (int t = 0; t < NT; ++t) {
        if (t + 1 < NT) issue_kv(t + 1, (t + 1) & 1);
        cp_wait<1>();
        __syncthreads();

        const uint32_t kbase = sbase + FK_OFF + (t & 1) * 8192;
        const uint32_t vbase = sbase + FV_OFF + (t & 1) * 8192;

        // ---- S = (Q/8) K^T : warp computes 16 x 64 ----
        float s[8][4];
#pragma unroll
        for (int nt = 0; nt < 8; nt++)
#pragma unroll
            for (int r = 0; r < 4; r++) s[nt][r] = 0.0f;

#pragma unroll
        for (int kc = 0; kc < 4; kc++) {
#pragma unroll
            for (int ntp = 0; ntp < 4; ntp++) {
                const int row = ntp * 16 + (kv_group >> 1) * 8 + kv_within;
                const int chunk = kc * 2 + (kv_group & 1);
                uint32_t b0a, b1a, b0b, b1b;
                ldsm_x4(b0a, b1a, b0b, b1b,
                        kbase + row * 128 + ((chunk ^ (row & 7)) * 16));
                mma_f16(s[ntp * 2][0], s[ntp * 2][1], s[ntp * 2][2], s[ntp * 2][3],
                        qa[kc][0], qa[kc][1], qa[kc][2], qa[kc][3], b0a, b1a);
                mma_f16(s[ntp * 2 + 1][0], s[ntp * 2 + 1][1],
                        s[ntp * 2 + 1][2], s[ntp * 2 + 1][3],
                        qa[kc][0], qa[kc][1], qa[kc][2], qa[kc][3], b0b, b1b);
            }
        }

        // ---- online softmax on fragments (rows lq, lq+8) ----
        float rm0 = -INFINITY, rm1 = -INFINITY;
#pragma unroll
        for (int nt = 0; nt < 8; nt++) {
            rm0 = fmaxf(rm0, fmaxf(s[nt][0], s[nt][1]));
            rm1 = fmaxf(rm1, fmaxf(s[nt][2], s[nt][3]));
        }
        rm0 = fmaxf(rm0, __shfl_xor_sync(0xffffffffu, rm0, 1));
        rm0 = fmaxf(rm0, __shfl_xor_sync(0xffffffffu, rm0, 2));
        rm1 = fmaxf(rm1, __shfl_xor_sync(0xffffffffu, rm1, 1));
        rm1 = fmaxf(rm1, __shfl_xor_sync(0xffffffffu, rm1, 2));
        const float mn0 = fmaxf(m0, rm0);
        const float mn1 = fmaxf(m1, rm1);
        const float alpha0 = __expf(m0 - mn0);
        const float alpha1 = __expf(m1 - mn1);

        float p[8][4];
        float rs0 = 0.0f, rs1 = 0.0f;
#pragma unroll
        for (int nt = 0; nt < 8; nt++) {
            p[nt][0] = __expf(s[nt][0] - mn0);
            p[nt][1] = __expf(s[nt][1] - mn0);
            p[nt][2] = __expf(s[nt][2] - mn1);
            p[nt][3] = __expf(s[nt][3] - mn1);
            rs0 += p[nt][0] + p[nt][1];
            rs1 += p[nt][2] + p[nt][3];
        }
        rs0 += __shfl_xor_sync(0xffffffffu, rs0, 1);
        rs0 += __shfl_xor_sync(0xffffffffu, rs0, 2);
        rs1 += __shfl_xor_sync(0xffffffffu, rs1, 1);
        rs1 += __shfl_xor_sync(0xffffffffu, rs1, 2);

        l0 = l0 * alpha0 + rs0;
        l1 = l1 * alpha1 + rs1;
        m0 = mn0;
        m1 = mn1;
#pragma unroll
        for (int nt = 0; nt < 8; nt++) {
            o[nt][0] *= alpha0; o[nt][1] *= alpha0;
            o[nt][2] *= alpha1; o[nt][3] *= alpha1;
        }

        // ---- P A-fragments straight from registers ----
        uint32_t pa[4][4];
#pragma unroll
        for (int kc = 0; kc < 4; kc++) {
            pa[kc][0] = pack_h2(p[2 * kc][0], p[2 * kc][1]);
            pa[kc][1] = pack_h2(p[2 * kc][2], p[2 * kc][3]);
            pa[kc][2] = pack_h2(p[2 * kc + 1][0], p[2 * kc + 1][1]);
            pa[kc][3] = pack_h2(p[2 * kc + 1][2], p[2 * kc + 1][3]);
        }

        // ---- O += P V : V via trans ldmatrix ----
#pragma unroll
        for (int kc = 0; kc < 4; kc++) {
#pragma unroll
            for (int ntp = 0; ntp < 4; ntp++) {
                const int row = kc * 16 + (kv_group & 1) * 8 + kv_within;
                const int chunk = ntp * 2 + (kv_group >> 1);
                uint32_t v0, v1, v2, v3;
                ldsm_x4_t(v0, v1, v2, v3,
                          vbase + row * 128 + ((chunk ^ (row & 7)) * 16));
                mma_f16(o[ntp * 2][0], o[ntp * 2][1], o[ntp * 2][2], o[ntp * 2][3],
                        pa[kc][0], pa[kc][1], pa[kc][2], pa[kc][3], v0, v1);
                mma_f16(o[ntp * 2 + 1][0], o[ntp * 2 + 1][1],
                        o[ntp * 2 + 1][2], o[ntp * 2 + 1][3],
                        pa[kc][0], pa[kc][1], pa[kc][2], pa[kc][3], v2, v3);
            }
        }
        __syncthreads();   // all reads of this KV buffer done before reuse
    }

    // ---- normalize + write fp16 ----
    const float inv0 = 1.0f / l0;
    const float inv1 = 1.0f / l1;
    const int r0 = q0 + w16 + lq;
    const int r1 = r0 + 8;
    const size_t base0 = ((size_t)(b * Tt + r0)) * Dd + h * HDd;
    const size_t base1 = ((size_t)(b * Tt + r1)) * Dd + h * HDd;
#pragma unroll
    for (int nt = 0; nt < 8; nt++) {
        const int c = nt * 8 + 2 * lr;
        *(__half2*)&Ob[base0 + c] =
            __floats2half2_rn(o[nt][0] * inv0, o[nt][1] * inv0);
        *(__half2*)&Ob[base1 + c] =
            __floats2half2_rn(o[nt][2] * inv1, o[nt][3] * inv1);
    }
}

// ---------------- residual add + LayerNorm ---------------------------------
__device__ __forceinline__ float block_sum_1024(float v, float* red) {
    const int tid = threadIdx.x;
    __syncthreads();
#pragma unroll
    for (int o = 16; o > 0; o >>= 1)
        v += __shfl_xor_sync(0xffffffffu, v, o);
    if ((tid & 31) == 0) red[tid >> 5] = v;
    __syncthreads();
    float t = (tid < 8) ? red[tid] : 0.0f;
    if (tid < 32) {
#pragma unroll
        for (int o = 4; o > 0; o >>= 1)
            t += __shfl_xor_sync(0xffffffffu, t, o);
        if (tid == 0) red[0] = t;
    }
    __syncthreads();
    return red[0];
}

__global__ __launch_bounds__(256) void add_ln_kernel(
    const float* __restrict__ A, const float* __restrict__ Bv,
    const float* __restrict__ g, const float* __restrict__ be,
    float* __restrict__ out, __half* __restrict__ outh)
{
    __shared__ float red[8];
    const int row = blockIdx.x;
    const int tid = threadIdx.x;
    const size_t base = (size_t)row * Dd;
    const int c = tid * 4;

    float4 a = *(const float4*)&A[base + c];
    float4 b = *(const float4*)&Bv[base + c];
    float v0 = a.x + b.x, v1 = a.y + b.y, v2 = a.z + b.z, v3 = a.w + b.w;

    float s = block_sum_1024(v0 + v1 + v2 + v3, red);
    const float mu = s * (1.0f / Dd);
    float d0 = v0 - mu, d1 = v1 - mu, d2 = v2 - mu, d3 = v3 - mu;
    float q = block_sum_1024(d0 * d0 + d1 * d1 + d2 * d2 + d3 * d3, red);
    const float inv = rsqrtf(q * (1.0f / Dd) + 1e-5f);

    float4 gv = *(const float4*)&g[c];
    float4 bev = *(const float4*)&be[c];
    float4 o;
    o.x = d0 * inv * gv.x + bev.x;
    o.y = d1 * inv * gv.y + bev.y;
    o.z = d2 * inv * gv.z + bev.z;
    o.w = d3 * inv * gv.w + bev.w;
    *(float4*)&out[base + c] = o;
    if (outh != nullptr) {
        *(__half2*)&outh[base + c]     = __floats2half2_rn(o.x, o.y);
        *(__half2*)&outh[base + c + 2] = __floats2half2_rn(o.z, o.w);
    }
}

// ---------------- orchestration --------------------------------------------
extern "C" void kernel_launch(void* const* d_in, const int* in_sizes, int n_in,
                              void* d_out, int out_size)
{
    const float* x   = (const float*)d_in[0];
    const float* wq  = (const float*)d_in[1];
    const float* wk  = (const float*)d_in[2];
    const float* wv  = (const float*)d_in[3];
    const float* wo  = (const float*)d_in[4];
    const float* w1  = (const float*)d_in[5];
    const float* b1  = (const float*)d_in[6];
    const float* w2  = (const float*)d_in[7];
    const float* b2  = (const float*)d_in[8];
    const float* g1  = (const float*)d_in[9];
    const float* be1 = (const float*)d_in[10];
    const float* g2  = (const float*)d_in[11];
    const float* be2 = (const float*)d_in[12];

    float *proj, *h, *ff2;
    __half *xh, *Qh, *Kh, *Vh, *attnh, *hh, *ff1h;
    __half *wqh, *wkh, *wvh, *woh, *w1h, *w2h;
    cudaGetSymbolAddress((void**)&proj,  g_proj);
    cudaGetSymbolAddress((void**)&h,     g_h);
    cudaGetSymbolAddress((void**)&ff2,   g_ff2);
    cudaGetSymbolAddress((void**)&xh,    g_xh);
    cudaGetSymbolAddress((void**)&Qh,    g_Qh);
    cudaGetSymbolAddress((void**)&Kh,    g_Kh);
    cudaGetSymbolAddress((void**)&Vh,    g_Vh);
    cudaGetSymbolAddress((void**)&attnh, g_attnh);
    cudaGetSymbolAddress((void**)&hh,    g_hh);
    cudaGetSymbolAddress((void**)&ff1h,  g_ff1h);
    cudaGetSymbolAddress((void**)&wqh,   g_wqh);
    cudaGetSymbolAddress((void**)&wkh,   g_wkh);
    cudaGetSymbolAddress((void**)&wvh,   g_wvh);
    cudaGetSymbolAddress((void**)&woh,   g_woh);
    cudaGetSymbolAddress((void**)&w1h,   g_w1h);
    cudaGetSymbolAddress((void**)&w2h,   g_w2h);

    cudaFuncSetAttribute(gemm_h_kernel<1, 0>,
                         cudaFuncAttributeMaxDynamicSharedMemorySize, HGEMM_SMEM);
    cudaFuncSetAttribute(gemm_h_kernel<0, 0>,
                         cudaFuncAttributeMaxDynamicSharedMemorySize, HGEMM_SMEM);
    cudaFuncSetAttribute(gemm_h_kernel<1, 2>,
                         cudaFuncAttributeMaxDynamicSharedMemorySize, HGEMM_SMEM);
    cudaFuncSetAttribute(gemm_h_kernel<0, 1>,
                         cudaFuncAttributeMaxDynamicSharedMemorySize, HGEMM_SMEM);
    cudaFuncSetAttribute(flash_h_kernel,
                         cudaFuncAttributeMaxDynamicSharedMemorySize, FH_SMEM);

    auto cvt = [](const float* in, __half* out, size_t n) {
        cvt_h_kernel<<<(unsigned)(n / 1024), 256>>>(in, out);
    };
    cvt(x,  xh,  (size_t)Mrows * Dd);
    cvt(wq, wqh, (size_t)Dd * Dd);
    cvt(wk, wkh, (size_t)Dd * Dd);
    cvt(wv, wvh, (size_t)Dd * Dd);
    cvt(wo, woh, (size_t)Dd * Dd);
    cvt(w1, w1h, (size_t)Dd * DFf);
    cvt(w2, w2h, (size_t)DFf * Dd);

    const dim3 gblk(256);
    const dim3 gD (Dd  / 128, Mrows / 128);   // (8, 64)
    const dim3 gDF(DFf / 128, Mrows / 128);   // (32, 64)

    gemm_h_kernel<1, 0><<<gD, gblk, HGEMM_SMEM>>>(xh, wqh, nullptr, Qh, Mrows, Dd, Dd);
    gemm_h_kernel<1, 0><<<gD, gblk, HGEMM_SMEM>>>(xh, wkh, nullptr, Kh, Mrows, Dd, Dd);
    gemm_h_kernel<1, 0><<<gD, gblk, HGEMM_SMEM>>>(xh, wvh, nullptr, Vh, Mrows, Dd, Dd);

    flash_h_kernel<<<dim3(Tt / 128, Bb * Hh), dim3(256), FH_SMEM>>>(Qh, Kh, Vh, attnh);

    gemm_h_kernel<0, 0><<<gD, gblk, HGEMM_SMEM>>>(attnh, woh, nullptr, proj, Mrows, Dd, Dd);

    add_ln_kernel<<<Mrows, 256>>>(x, proj, g1, be1, h, hh);

    gemm_h_kernel<1, 2><<<gDF, gblk, HGEMM_SMEM>>>(hh, w1h, b1, ff1h, Mrows, DFf, Dd);
    gemm_h_kernel<0, 1><<<gD,  gblk, HGEMM_SMEM>>>(ff1h, w2h, b2, ff2, Mrows, Dd, DFf);

    add_ln_kernel<<<Mrows, 256>>>(h, ff2, g2, be2, (float*)d_out, nullptr);
}

// round 12
// speedup vs baseline: 2.3210x; 1.0442x over previous
#include <cuda_runtime.h>
#include <cuda_fp16.h>
#include <math.h>
#include <stdint.h>

// Problem shape (fixed)
static constexpr int Bb = 4;
static constexpr int Tt = 2048;
static constexpr int Dd = 1024;
static constexpr int Hh = 16;
static constexpr int HDd = 64;
static constexpr int DFf = 4096;
static constexpr int Mrows = Bb * Tt;   // 8192
static constexpr int D3 = 3 * Dd;       // 3072

// ---------------- scratch (device globals; no allocation allowed) ----------
__device__ float g_proj[(size_t)Mrows * Dd];
__device__ float g_h[(size_t)Mrows * Dd];
__device__ float g_ff2[(size_t)Mrows * Dd];
// fp16 activations / weights
__device__ __half g_xh[(size_t)Mrows * Dd];
__device__ __half g_qkvh[(size_t)Mrows * D3];
__device__ __half g_attnh[(size_t)Mrows * Dd];
__device__ __half g_hh[(size_t)Mrows * Dd];
__device__ __half g_ff1h[(size_t)Mrows * DFf];
__device__ __half g_wqkvh[(size_t)Dd * D3];
__device__ __half g_woh[(size_t)Dd * Dd];
__device__ __half g_w1h[(size_t)Dd * DFf];
__device__ __half g_w2h[(size_t)DFf * Dd];

// ---------------- helpers ----------------
__device__ __forceinline__ float gelu_exact(float x) {
    return 0.5f * x * (1.0f + erff(x * 0.70710678118654752f));
}

__device__ __forceinline__ void cp_async16(uint32_t smem_addr, const void* gptr) {
    asm volatile("cp.async.cg.shared.global [%0], [%1], 16;\n"
                 :: "r"(smem_addr), "l"(gptr));
}
__device__ __forceinline__ void cp_commit() {
    asm volatile("cp.async.commit_group;\n");
}
template <int N>
__device__ __forceinline__ void cp_wait() {
    asm volatile("cp.async.wait_group %0;\n" :: "n"(N));
}

__device__ __forceinline__ uint32_t smem_u32(const void* p) {
    return (uint32_t)__cvta_generic_to_shared(p);
}

__device__ __forceinline__ void mma_f16(
    float& c0, float& c1, float& c2, float& c3,
    uint32_t a0, uint32_t a1, uint32_t a2, uint32_t a3,
    uint32_t b0, uint32_t b1)
{
    asm volatile(
        "mma.sync.aligned.m16n8k16.row.col.f32.f16.f16.f32 "
        "{%0,%1,%2,%3}, {%4,%5,%6,%7}, {%8,%9}, {%0,%1,%2,%3};\n"
        : "+f"(c0), "+f"(c1), "+f"(c2), "+f"(c3)
        : "r"(a0), "r"(a1), "r"(a2), "r"(a3), "r"(b0), "r"(b1));
}

__device__ __forceinline__ void ldsm_x4(
    uint32_t& r0, uint32_t& r1, uint32_t& r2, uint32_t& r3, uint32_t addr)
{
    asm volatile("ldmatrix.sync.aligned.m8n8.x4.shared.b16 {%0,%1,%2,%3}, [%4];"
                 : "=r"(r0), "=r"(r1), "=r"(r2), "=r"(r3) : "r"(addr));
}
__device__ __forceinline__ void ldsm_x4_t(
    uint32_t& r0, uint32_t& r1, uint32_t& r2, uint32_t& r3, uint32_t addr)
{
    asm volatile("ldmatrix.sync.aligned.m8n8.x4.trans.shared.b16 {%0,%1,%2,%3}, [%4];"
                 : "=r"(r0), "=r"(r1), "=r"(r2), "=r"(r3) : "r"(addr));
}

__device__ __forceinline__ uint32_t pack_h2(float a, float b) {
    __half2 h = __floats2half2_rn(a, b);
    return *(uint32_t*)&h;
}

// ---------------- fp16 tensor-core GEMM, cp.async 4-stage -------------------
// C[M,N] = A[M,K] @ B[K,N] (+bias)(+gelu).
// Block 128x128, BK=32, 128 threads (4 warps), warp tile 64x64.
static constexpr int HAS_B = 80;                     // A row bytes
static constexpr int HA_BYTES = 128 * HAS_B;         // 10240
static constexpr int HB_BYTES = 32 * 256;            // 8192
static constexpr int HSTAGE = HA_BYTES + HB_BYTES;   // 18432
static constexpr int HSTAGES = 4;
static constexpr int HGEMM_SMEM = HSTAGES * HSTAGE;  // 73728 B

// OUTH: 0 = float out, 1 = half out.  EPI: 0 none, 1 +bias, 2 +bias+gelu
template <int OUTH, int EPI>
__global__ __launch_bounds__(128) void gemm_h_kernel(
    const __half* __restrict__ A, const __half* __restrict__ Bm,
    const float* __restrict__ bias, void* __restrict__ Cout,
    int M, int N, int K)
{
    extern __shared__ __align__(128) char smem[];
    const uint32_t sbase = smem_u32(smem);

    const int tid = threadIdx.x;
    const int warp = tid >> 5;
    const int lane = tid & 31;
    const int lq = lane >> 2;
    const int lr = lane & 3;

    const int bm = blockIdx.y * 128;
    const int bn = blockIdx.x * 128;
    const int wm = (warp & 1) * 64;
    const int wn = (warp >> 1) * 64;

    // A: 512 16B-chunks (128 rows x 4); 4 per thread
    // B: 512 chunks (32 rows x 16); 4 per thread
    int a_r[4], b_k[4];
    uint32_t sa[4], sb[4];
    const int a_c = tid & 3;
    const int b_c = tid & 15;
#pragma unroll
    for (int i = 0; i < 4; i++) {
        const int ida = tid + i * 128;
        a_r[i] = ida >> 2;
        sa[i] = a_r[i] * HAS_B + a_c * 16;
        const int idb = tid + i * 128;
        b_k[i] = idb >> 4;
        sb[i] = HA_BYTES + b_k[i] * 256 + ((b_c ^ (b_k[i] & 7)) * 16);
    }

    const __half* Ag = A + (size_t)bm * K;
    const __half* Bg = Bm + bn;

    auto issue = [&](int kt, int stage) {
        const uint32_t st = sbase + stage * HSTAGE;
        const int k0 = kt * 32;
#pragma unroll
        for (int i = 0; i < 4; i++) {
            cp_async16(st + sa[i], Ag + (size_t)a_r[i] * K + k0 + a_c * 8);
            cp_async16(st + sb[i], Bg + (size_t)(k0 + b_k[i]) * N + b_c * 8);
        }
        cp_commit();
    };

    const int KT = K / 32;
#pragma unroll
    for (int s = 0; s < HSTAGES - 1; s++) issue(s, s);

    float acc[4][8][4];
#pragma unroll
    for (int i = 0; i < 4; i++)
#pragma unroll
        for (int j = 0; j < 8; j++)
#pragma unroll
            for (int r = 0; r < 4; r++) acc[i][j][r] = 0.0f;

    const int a_lrow = lane & 15;
    const int a_lkof = (lane >> 4) * 16;
    const int b_lrow = lane & 15;
    const int b_lnof = (lane >> 4) * 8;

    for (int it = 0; it < KT; ++it) {
        cp_wait<HSTAGES - 2>();
        __syncthreads();
        if (it + HSTAGES - 1 < KT) issue(it + HSTAGES - 1, (it + HSTAGES - 1) & 3);

        const uint32_t Asb = sbase + (it & 3) * HSTAGE;
        const uint32_t Bsb = Asb + HA_BYTES;

#pragma unroll
        for (int kk = 0; kk < 32; kk += 16) {
            uint32_t af[4][4];
#pragma unroll
            for (int mt = 0; mt < 4; mt++) {
                const int row = wm + mt * 16 + a_lrow;
                ldsm_x4(af[mt][0], af[mt][1], af[mt][2], af[mt][3],
                        Asb + row * HAS_B + kk * 2 + a_lkof);
            }
            uint32_t bf[8][2];
#pragma unroll
            for (int pr = 0; pr < 4; pr++) {
                const int r = kk + b_lrow;
                const int n0 = wn + pr * 16 + b_lnof;
                const uint32_t addr =
                    Bsb + r * 256 + (((n0 >> 3) ^ (r & 7)) * 16);
                ldsm_x4_t(bf[pr * 2][0], bf[pr * 2][1],
                          bf[pr * 2 + 1][0], bf[pr * 2 + 1][1], addr);
            }
#pragma unroll
            for (int mt = 0; mt < 4; mt++)
#pragma unroll
                for (int nt = 0; nt < 8; nt++)
                    mma_f16(acc[mt][nt][0], acc[mt][nt][1],
                            acc[mt][nt][2], acc[mt][nt][3],
                            af[mt][0], af[mt][1], af[mt][2], af[mt][3],
                            bf[nt][0], bf[nt][1]);
        }
        __syncthreads();
    }

#pragma unroll
    for (int mt = 0; mt < 4; mt++) {
#pragma unroll
        for (int nt = 0; nt < 8; nt++) {
            const int col = bn + wn + nt * 8 + 2 * lr;
#pragma unroll
            for (int half_i = 0; half_i < 2; half_i++) {
                const int row = bm + wm + mt * 16 + lq + half_i * 8;
                float v0 = acc[mt][nt][half_i * 2 + 0];
                float v1 = acc[mt][nt][half_i * 2 + 1];
                if (EPI >= 1) {
                    v0 += bias[col];
                    v1 += bias[col + 1];
                }
                if (EPI == 2) {
                    v0 = gelu_exact(v0);
                    v1 = gelu_exact(v1);
                }
                if (OUTH) {
                    __half2 hv = __floats2half2_rn(v0, v1);
                    *(__half2*)((__half*)Cout + (size_t)row * N + col) = hv;
                } else {
                    *(float2*)((float*)Cout + (size_t)row * N + col) =
                        make_float2(v0, v1);
                }
            }
        }
    }
}

// ---------------- fp32 -> fp16 converts -------------------------------------
__global__ __launch_bounds__(256) void cvt_h_kernel(
    const float* __restrict__ in, __half* __restrict__ out)
{
    const size_t i = ((size_t)blockIdx.x * 256 + threadIdx.x) * 4;
    float4 v = *(const float4*)&in[i];
    *(__half2*)&out[i]     = __floats2half2_rn(v.x, v.y);
    *(__half2*)&out[i + 2] = __floats2half2_rn(v.z, v.w);
}

// in: [R][C] fp32; out: [R][ldo] fp16 at column offset coff
__global__ __launch_bounds__(256) void cvt_h_strided_kernel(
    const float* __restrict__ in, __half* __restrict__ out,
    int C, int ldo, int coff)
{
    const size_t i = ((size_t)blockIdx.x * 256 + threadIdx.x) * 4;
    const int r = (int)(i / C);
    const int c = (int)(i % C);
    float4 v = *(const float4*)&in[i];
    __half* o = out + (size_t)r * ldo + coff + c;
    *(__half2*)&o[0] = __floats2half2_rn(v.x, v.y);
    *(__half2*)&o[2] = __floats2half2_rn(v.z, v.w);
}

// ---------------- fp16 flash attention --------------------------------------
// Q/K/V read from one [M][ldqkv] buffer at column offsets 0/Dd/2Dd (+h*64).
static constexpr int FQ_OFF = 0;                 // 128 rows * 128 B = 16 KB
static constexpr int FK_OFF = 16384;             // 2 x 8 KB
static constexpr int FV_OFF = 32768;             // 2 x 8 KB
static constexpr int FH_SMEM = 49152;

__global__ __launch_bounds__(256) void flash_h_kernel(
    const __half* __restrict__ QKV, int ldqkv, __half* __restrict__ Ob)
{
    extern __shared__ __align__(128) char fsm[];
    const uint32_t sbase = smem_u32(fsm);

    const int tid = threadIdx.x;
    const int warp = tid >> 5;
    const int lane = tid & 31;
    const int lq = lane >> 2;
    const int lr = lane & 3;

    const int b = blockIdx.y / Hh;
    const int h = blockIdx.y % Hh;
    const int q0 = blockIdx.x * 128;
    const int w16 = warp * 16;

    const __half* Qb = QKV + h * HDd;
    const __half* Kb = QKV + Dd + h * HDd;
    const __half* Vb = QKV + 2 * Dd + h * HDd;

    int kv_r[2], kv_c[2];
#pragma unroll
    for (int it = 0; it < 2; it++) {
        const int id = tid + it * 256;
        kv_r[it] = id >> 3;
        kv_c[it] = id & 7;
    }

    auto issue_kv = [&](int tile, int buf) {
        const size_t baseKV = ((size_t)(b * Tt + tile * 64)) * ldqkv;
        const uint32_t kst = sbase + FK_OFF + buf * 8192;
        const uint32_t vst = sbase + FV_OFF + buf * 8192;
#pragma unroll
        for (int it = 0; it < 2; it++) {
            const int r = kv_r[it], c = kv_c[it];
            const size_t g = baseKV + (size_t)r * ldqkv + c * 8;
            const uint32_t so = r * 128 + ((c ^ (r & 7)) * 16);
            cp_async16(kst + so, Kb + g);
            cp_async16(vst + so, Vb + g);
        }
        cp_commit();
    };

    issue_kv(0, 0);

    // stage Q tile [128 x 64] (swizzled)
    {
        const size_t baseQ = ((size_t)(b * Tt + q0)) * ldqkv;
#pragma unroll
        for (int it = 0; it < 4; it++) {
            const int id = tid + it * 256;
            const int r = id >> 3, c = id & 7;
            uint4 v = *(const uint4*)&Qb[baseQ + (size_t)r * ldqkv + c * 8];
            *(uint4*)(fsm + FQ_OFF + r * 128 + ((c ^ (r & 7)) * 16)) = v;
        }
    }
    __syncthreads();

    uint32_t qa[4][4];
    {
        const int arow = w16 + (lane & 15);
        const __half2 sc2 = __float2half2_rn(0.125f);
#pragma unroll
        for (int kc = 0; kc < 4; kc++) {
            const int chunk = kc * 2 + (lane >> 4);
            const uint32_t addr =
                sbase + FQ_OFF + arow * 128 + ((chunk ^ (arow & 7)) * 16);
            ldsm_x4(qa[kc][0], qa[kc][1], qa[kc][2], qa[kc][3], addr);
#pragma unroll
            for (int r = 0; r < 4; r++) {
                __half2 t = *(__half2*)&qa[kc][r];
                t = __hmul2(t, sc2);
                qa[kc][r] = *(uint32_t*)&t;
            }
        }
    }

    float o[8][4];
#pragma unroll
    for (int nt = 0; nt < 8; nt++)
#pragma unroll
        for (int r = 0; r < 4; r++) o[nt][r] = 0.0f;
    float m0 = -INFINITY, m1 = -INFINITY;
    float l0 = 0.0f, l1 = 0.0f;

    const int kv_group = lane >> 3;
    const int kv_within = lane & 7;

    const int NT = Tt / 64;
    for (int t = 0; t < NT; ++t) {
        if (t + 1 < NT) issue_kv(t + 1, (t + 1) & 1);
        cp_wait<1>();
        __syncthreads();

        const uint32_t kbase = sbase + FK_OFF + (t & 1) * 8192;
        const uint32_t vbase = sbase + FV_OFF + (t & 1) * 8192;

        float s[8][4];
#pragma unroll
        for (int nt = 0; nt < 8; nt++)
#pragma unroll
            for (int r = 0; r < 4; r++) s[nt][r] = 0.0f;

#pragma unroll
        for (int kc = 0; kc < 4; kc++) {
#pragma unroll
            for (int ntp = 0; ntp < 4; ntp++) {
                const int row = ntp * 16 + (kv_group >> 1) * 8 + kv_within;
                const int chunk = kc * 2 + (kv_group & 1);
                uint32_t b0a, b1a, b0b, b1b;
                ldsm_x4(b0a, b1a, b0b, b1b,
                        kbase + row * 128 + ((chunk ^ (row & 7)) * 16));
                mma_f16(s[ntp * 2][0], s[ntp * 2][1], s[ntp * 2][2], s[ntp * 2][3],
                        qa[kc][0], qa[kc][1], qa[kc][2], qa[kc][3], b0a, b1a);
                mma_f16(s[ntp * 2 + 1][0], s[ntp * 2 + 1][1],
                        s[ntp * 2 + 1][2], s[ntp * 2 + 1][3],
                        qa[kc][0], qa[kc][1], qa[kc][2], qa[kc][3], b0b, b1b);
            }
        }

        float rm0 = -INFINITY, rm1 = -INFINITY;
#pragma unroll
        for (int nt = 0; nt < 8; nt++) {
            rm0 = fmaxf(rm0, fmaxf(s[nt][0], s[nt][1]));
            rm1 = fmaxf(rm1, fmaxf(s[nt][2], s[nt][3]));
        }
        rm0 = fmaxf(rm0, __shfl_xor_sync(0xffffffffu, rm0, 1));
        rm0 = fmaxf(rm0, __shfl_xor_sync(0xffffffffu, rm0, 2));
        rm1 = fmaxf(rm1, __shfl_xor_sync(0xffffffffu, rm1, 1));
        rm1 = fmaxf(rm1, __shfl_xor_sync(0xffffffffu, rm1, 2));
        const float mn0 = fmaxf(m0, rm0);
        const float mn1 = fmaxf(m1, rm1);
        const float alpha0 = __expf(m0 - mn0);
        const float alpha1 = __expf(m1 - mn1);

        float p[8][4];
        float rs0 = 0.0f, rs1 = 0.0f;
#pragma unroll
        for (int nt = 0; nt < 8; nt++) {
            p[nt][0] = __expf(s[nt][0] - mn0);
            p[nt][1] = __expf(s[nt][1] - mn0);
            p[nt][2] = __expf(s[nt][2] - mn1);
            p[nt][3] = __expf(s[nt][3] - mn1);
            rs0 += p[nt][0] + p[nt][1];
            rs1 += p[nt][2] + p[nt][3];
        }
        rs0 += __shfl_xor_sync(0xffffffffu, rs0, 1);
        rs0 += __shfl_xor_sync(0xffffffffu, rs0, 2);
        rs1 += __shfl_xor_sync(0xffffffffu, rs1, 1);
        rs1 += __shfl_xor_sync(0xffffffffu, rs1, 2);

        l0 = l0 * alpha0 + rs0;
        l1 = l1 * alpha1 + rs1;
        m0 = mn0;
        m1 = mn1;
#pragma unroll
        for (int nt = 0; nt < 8; nt++) {
            o[nt][0] *= alpha0; o[nt][1] *= alpha0;
            o[nt][2] *= alpha1; o[nt][3] *= alpha1;
        }

        uint32_t pa[4][4];
#pragma unroll
        for (int kc = 0; kc < 4; kc++) {
            pa[kc][0] = pack_h2(p[2 * kc][0], p[2 * kc][1]);
            pa[kc][1] = pack_h2(p[2 * kc][2], p[2 * kc][3]);
            pa[kc][2] = pack_h2(p[2 * kc + 1][0], p[2 * kc + 1][1]);
            pa[kc][3] = pack_h2(p[2 * kc + 1][2], p[2 * kc + 1][3]);
        }

#pragma unroll
        for (int kc = 0; kc < 4; kc++) {
#pragma unroll
            for (int ntp = 0; ntp < 4; ntp++) {
                const int row = kc * 16 + (kv_group & 1) * 8 + kv_within;
                const int chunk = ntp * 2 + (kv_group >> 1);
                uint32_t v0, v1, v2, v3;
                ldsm_x4_t(v0, v1, v2, v3,
                          vbase + row * 128 + ((chunk ^ (row & 7)) * 16));
                mma_f16(o[ntp * 2][0], o[ntp * 2][1], o[ntp * 2][2], o[ntp * 2][3],
                        pa[kc][0], pa[kc][1], pa[kc][2], pa[kc][3], v0, v1);
                mma_f16(o[ntp * 2 + 1][0], o[ntp * 2 + 1][1],
                        o[ntp * 2 + 1][2], o[ntp * 2 + 1][3],
                        pa[kc][0], pa[kc][1], pa[kc][2], pa[kc][3], v2, v3);
            }
        }
        __syncthreads();
    }

    const float inv0 = 1.0f / l0;
    const float inv1 = 1.0f / l1;
    const int r0 = q0 + w16 + lq;
    const int r1 = r0 + 8;
    const size_t base0 = ((size_t)(b * Tt + r0)) * Dd + h * HDd;
    const size_t base1 = ((size_t)(b * Tt + r1)) * Dd + h * HDd;
#pragma unroll
    for (int nt = 0; nt < 8; nt++) {
        const int c = nt * 8 + 2 * lr;
        *(__half2*)&Ob[base0 + c] =
            __floats2half2_rn(o[nt][0] * inv0, o[nt][1] * inv0);
        *(__half2*)&Ob[base1 + c] =
            __floats2half2_rn(o[nt][2] * inv1, o[nt][3] * inv1);
    }
}

// ---------------- residual add + LayerNorm ---------------------------------
__device__ __forceinline__ float block_sum_1024(float v, float* red) {
    const int tid = threadIdx.x;
    __syncthreads();
#pragma unroll
    for (int o = 16; o > 0; o >>= 1)
        v += __shfl_xor_sync(0xffffffffu, v, o);
    if ((tid & 31) == 0) red[tid >> 5] = v;
    __syncthreads();
    float t = (tid < 8) ? red[tid] : 0.0f;
    if (tid < 32) {
#pragma unroll
        for (int o = 4; o > 0; o >>= 1)
            t += __shfl_xor_sync(0xffffffffu, t, o);
        if (tid == 0) red[0] = t;
    }
    __syncthreads();
    return red[0];
}

__global__ __launch_bounds__(256) void add_ln_kernel(
    const float* __restrict__ A, const float* __restrict__ Bv,
    const float* __restrict__ g, const float* __restrict__ be,
    float* __restrict__ out, __half* __restrict__ outh)
{
    __shared__ float red[8];
    const int row = blockIdx.x;
    const int tid = threadIdx.x;
    const size_t base = (size_t)row * Dd;
    const int c = tid * 4;

    float4 a = *(const float4*)&A[base + c];
    float4 b = *(const float4*)&Bv[base + c];
    float v0 = a.x + b.x, v1 = a.y + b.y, v2 = a.z + b.z, v3 = a.w + b.w;

    float s = block_sum_1024(v0 + v1 + v2 + v3, red);
    const float mu = s * (1.0f / Dd);
    float d0 = v0 - mu, d1 = v1 - mu, d2 = v2 - mu, d3 = v3 - mu;
    float q = block_sum_1024(d0 * d0 + d1 * d1 + d2 * d2 + d3 * d3, red);
    const float inv = rsqrtf(q * (1.0f / Dd) + 1e-5f);

    float4 gv = *(const float4*)&g[c];
    float4 bev = *(const float4*)&be[c];
    float4 o;
    o.x = d0 * inv * gv.x + bev.x;
    o.y = d1 * inv * gv.y + bev.y;
    o.z = d2 * inv * gv.z + bev.z;
    o.w = d3 * inv * gv.w + bev.w;
    *(float4*)&out[base + c] = o;
    if (outh != nullptr) {
        *(__half2*)&outh[base + c]     = __floats2half2_rn(o.x, o.y);
        *(__half2*)&outh[base + c + 2] = __floats2half2_rn(o.z, o.w);
    }
}

// ---------------- orchestration --------------------------------------------
extern "C" void kernel_launch(void* const* d_in, const int* in_sizes, int n_in,
                              void* d_out, int out_size)
{
    const float* x   = (const float*)d_in[0];
    const float* wq  = (const float*)d_in[1];
    const float* wk  = (const float*)d_in[2];
    const float* wv  = (const float*)d_in[3];
    const float* wo  = (const float*)d_in[4];
    const float* w1  = (const float*)d_in[5];
    const float* b1  = (const float*)d_in[6];
    const float* w2  = (const float*)d_in[7];
    const float* b2  = (const float*)d_in[8];
    const float* g1  = (const float*)d_in[9];
    const float* be1 = (const float*)d_in[10];
    const float* g2  = (const float*)d_in[11];
    const float* be2 = (const float*)d_in[12];

    float *proj, *h, *ff2;
    __half *xh, *qkvh, *attnh, *hh, *ff1h, *wqkvh, *woh, *w1h, *w2h;
    cudaGetSymbolAddress((void**)&proj,  g_proj);
    cudaGetSymbolAddress((void**)&h,     g_h);
    cudaGetSymbolAddress((void**)&ff2,   g_ff2);
    cudaGetSymbolAddress((void**)&xh,    g_xh);
    cudaGetSymbolAddress((void**)&qkvh,  g_qkvh);
    cudaGetSymbolAddress((void**)&attnh, g_attnh);
    cudaGetSymbolAddress((void**)&hh,    g_hh);
    cudaGetSymbolAddress((void**)&ff1h,  g_ff1h);
    cudaGetSymbolAddress((void**)&wqkvh, g_wqkvh);
    cudaGetSymbolAddress((void**)&woh,   g_woh);
    cudaGetSymbolAddress((void**)&w1h,   g_w1h);
    cudaGetSymbolAddress((void**)&w2h,   g_w2h);

    cudaFuncSetAttribute(gemm_h_kernel<1, 0>,
                         cudaFuncAttributeMaxDynamicSharedMemorySize, HGEMM_SMEM);
    cudaFuncSetAttribute(gemm_h_kernel<0, 0>,
                         cudaFuncAttributeMaxDynamicSharedMemorySize, HGEMM_SMEM);
    cudaFuncSetAttribute(gemm_h_kernel<1, 2>,
                         cudaFuncAttributeMaxDynamicSharedMemorySize, HGEMM_SMEM);
    cudaFuncSetAttribute(gemm_h_kernel<0, 1>,
                         cudaFuncAttributeMaxDynamicSharedMemorySize, HGEMM_SMEM);
    cudaFuncSetAttribute(flash_h_kernel,
                         cudaFuncAttributeMaxDynamicSharedMemorySize, FH_SMEM);

    auto cvt = [](const float* in, __half* out, size_t n) {
        cvt_h_kernel<<<(unsigned)(n / 1024), 256>>>(in, out);
    };
    cvt(x,  xh,  (size_t)Mrows * Dd);
    // wq/wk/wv -> one [Dd][3*Dd] buffer at column offsets 0/Dd/2Dd
    cvt_h_strided_kernel<<<(unsigned)((size_t)Dd * Dd / 1024), 256>>>(
        wq, wqkvh, Dd, D3, 0);
    cvt_h_strided_kernel<<<(unsigned)((size_t)Dd * Dd / 1024), 256>>>(
        wk, wqkvh, Dd, D3, Dd);
    cvt_h_strided_kernel<<<(unsigned)((size_t)Dd * Dd / 1024), 256>>>(
        wv, wqkvh, Dd, D3, 2 * Dd);
    cvt(wo, woh, (size_t)Dd * Dd);
    cvt(w1, w1h, (size_t)Dd * DFf);
    cvt(w2, w2h, (size_t)DFf * Dd);

    const dim3 gblk(128);
    const dim3 gQKV(D3  / 128, Mrows / 128);  // (24, 64)
    const dim3 gD  (Dd  / 128, Mrows / 128);  // (8, 64)
    const dim3 gDF (DFf / 128, Mrows / 128);  // (32, 64)

    // fused QKV: [Mrows][3072] fp16
    gemm_h_kernel<1, 0><<<gQKV, gblk, HGEMM_SMEM>>>(xh, wqkvh, nullptr, qkvh,
                                                    Mrows, D3, Dd);

    flash_h_kernel<<<dim3(Tt / 128, Bb * Hh), dim3(256), FH_SMEM>>>(qkvh, D3, attnh);

    gemm_h_kernel<0, 0><<<gD, gblk, HGEMM_SMEM>>>(attnh, woh, nullptr, proj,
                                                  Mrows, Dd, Dd);

    add_ln_kernel<<<Mrows, 256>>>(x, proj, g1, be1, h, hh);

    gemm_h_kernel<1, 2><<<gDF, gblk, HGEMM_SMEM>>>(hh, w1h, b1, ff1h, Mrows, DFf, Dd);
    gemm_h_kernel<0, 1><<<gD,  gblk, HGEMM_SMEM>>>(ff1h, w2h, b2, ff2, Mrows, Dd, DFf);

    add_ln_kernel<<<Mrows, 256>>>(h, ff2, g2, be2, (float*)d_out, nullptr);
}

// round 13
// speedup vs baseline: 2.3259x; 1.0021x over previous
#include <cuda_runtime.h>
#include <cuda_fp16.h>
#include <math.h>
#include <stdint.h>

// Problem shape (fixed)
static constexpr int Bb = 4;
static constexpr int Tt = 2048;
static constexpr int Dd = 1024;
static constexpr int Hh = 16;
static constexpr int HDd = 64;
static constexpr int DFf = 4096;
static constexpr int Mrows = Bb * Tt;   // 8192
static constexpr int D3 = 3 * Dd;       // 3072

// ---------------- scratch (device globals; no allocation allowed) ----------
__device__ float g_proj[(size_t)Mrows * Dd];
__device__ float g_h[(size_t)Mrows * Dd];
__device__ float g_ff2[(size_t)Mrows * Dd];
// fp16 activations / weights
__device__ __half g_xh[(size_t)Mrows * Dd];
__device__ __half g_qkvh[(size_t)Mrows * D3];
__device__ __half g_attnh[(size_t)Mrows * Dd];
__device__ __half g_hh[(size_t)Mrows * Dd];
__device__ __half g_ff1h[(size_t)Mrows * DFf];
__device__ __half g_wqkvh[(size_t)Dd * D3];
__device__ __half g_woh[(size_t)Dd * Dd];
__device__ __half g_w1h[(size_t)Dd * DFf];
__device__ __half g_w2h[(size_t)DFf * Dd];

// ---------------- helpers ----------------
__device__ __forceinline__ float gelu_exact(float x) {
    return 0.5f * x * (1.0f + erff(x * 0.70710678118654752f));
}

__device__ __forceinline__ void cp_async16(uint32_t smem_addr, const void* gptr) {
    asm volatile("cp.async.cg.shared.global [%0], [%1], 16;\n"
                 :: "r"(smem_addr), "l"(gptr));
}
__device__ __forceinline__ void cp_commit() {
    asm volatile("cp.async.commit_group;\n");
}
template <int N>
__device__ __forceinline__ void cp_wait() {
    asm volatile("cp.async.wait_group %0;\n" :: "n"(N));
}

__device__ __forceinline__ uint32_t smem_u32(const void* p) {
    return (uint32_t)__cvta_generic_to_shared(p);
}

__device__ __forceinline__ void mma_f16(
    float& c0, float& c1, float& c2, float& c3,
    uint32_t a0, uint32_t a1, uint32_t a2, uint32_t a3,
    uint32_t b0, uint32_t b1)
{
    asm volatile(
        "mma.sync.aligned.m16n8k16.row.col.f32.f16.f16.f32 "
        "{%0,%1,%2,%3}, {%4,%5,%6,%7}, {%8,%9}, {%0,%1,%2,%3};\n"
        : "+f"(c0), "+f"(c1), "+f"(c2), "+f"(c3)
        : "r"(a0), "r"(a1), "r"(a2), "r"(a3), "r"(b0), "r"(b1));
}

__device__ __forceinline__ void ldsm_x4(
    uint32_t& r0, uint32_t& r1, uint32_t& r2, uint32_t& r3, uint32_t addr)
{
    asm volatile("ldmatrix.sync.aligned.m8n8.x4.shared.b16 {%0,%1,%2,%3}, [%4];"
                 : "=r"(r0), "=r"(r1), "=r"(r2), "=r"(r3) : "r"(addr));
}
__device__ __forceinline__ void ldsm_x4_t(
    uint32_t& r0, uint32_t& r1, uint32_t& r2, uint32_t& r3, uint32_t addr)
{
    asm volatile("ldmatrix.sync.aligned.m8n8.x4.trans.shared.b16 {%0,%1,%2,%3}, [%4];"
                 : "=r"(r0), "=r"(r1), "=r"(r2), "=r"(r3) : "r"(addr));
}

__device__ __forceinline__ uint32_t pack_h2(float a, float b) {
    __half2 h = __floats2half2_rn(a, b);
    return *(uint32_t*)&h;
}

// ---------------- fp16 tensor-core GEMM, cp.async 4-stage -------------------
// C[M,N] = A[M,K] @ B[K,N] (+bias)(+gelu).
// Block 128x128, BK=32, 128 threads (4 warps), warp tile 64x64.
static constexpr int HAS_B = 80;                     // A row bytes
static constexpr int HA_BYTES = 128 * HAS_B;         // 10240
static constexpr int HB_BYTES = 32 * 256;            // 8192
static constexpr int HSTAGE = HA_BYTES + HB_BYTES;   // 18432
static constexpr int HSTAGES = 4;
static constexpr int HGEMM_SMEM = HSTAGES * HSTAGE;  // 73728 B

// OUTH: 0 = float out, 1 = half out.  EPI: 0 none, 1 +bias, 2 +bias+gelu
template <int OUTH, int EPI>
__global__ __launch_bounds__(128) void gemm_h_kernel(
    const __half* __restrict__ A, const __half* __restrict__ Bm,
    const float* __restrict__ bias, void* __restrict__ Cout,
    int M, int N, int K)
{
    extern __shared__ __align__(128) char smem[];
    const uint32_t sbase = smem_u32(smem);

    const int tid = threadIdx.x;
    const int warp = tid >> 5;
    const int lane = tid & 31;
    const int lq = lane >> 2;
    const int lr = lane & 3;

    const int bm = blockIdx.y * 128;
    const int bn = blockIdx.x * 128;
    const int wm = (warp & 1) * 64;
    const int wn = (warp >> 1) * 64;

    // A: 512 16B-chunks (128 rows x 4); 4 per thread
    // B: 512 chunks (32 rows x 16); 4 per thread
    int a_r[4], b_k[4];
    uint32_t sa[4], sb[4];
    const int a_c = tid & 3;
    const int b_c = tid & 15;
#pragma unroll
    for (int i = 0; i < 4; i++) {
        const int ida = tid + i * 128;
        a_r[i] = ida >> 2;
        sa[i] = a_r[i] * HAS_B + a_c * 16;
        const int idb = tid + i * 128;
        b_k[i] = idb >> 4;
        sb[i] = HA_BYTES + b_k[i] * 256 + ((b_c ^ (b_k[i] & 7)) * 16);
    }

    const __half* Ag = A + (size_t)bm * K;
    const __half* Bg = Bm + bn;

    auto issue = [&](int kt, int stage) {
        const uint32_t st = sbase + stage * HSTAGE;
        const int k0 = kt * 32;
#pragma unroll
        for (int i = 0; i < 4; i++) {
            cp_async16(st + sa[i], Ag + (size_t)a_r[i] * K + k0 + a_c * 8);
            cp_async16(st + sb[i], Bg + (size_t)(k0 + b_k[i]) * N + b_c * 8);
        }
        cp_commit();
    };

    const int KT = K / 32;
#pragma unroll
    for (int s = 0; s < HSTAGES - 1; s++) issue(s, s);

    float acc[4][8][4];
#pragma unroll
    for (int i = 0; i < 4; i++)
#pragma unroll
        for (int j = 0; j < 8; j++)
#pragma unroll
            for (int r = 0; r < 4; r++) acc[i][j][r] = 0.0f;

    const int a_lrow = lane & 15;
    const int a_lkof = (lane >> 4) * 16;
    const int b_lrow = lane & 15;
    const int b_lnof = (lane >> 4) * 8;

    for (int it = 0; it < KT; ++it) {
        cp_wait<HSTAGES - 2>();
        __syncthreads();
        if (it + HSTAGES - 1 < KT) issue(it + HSTAGES - 1, (it + HSTAGES - 1) & 3);

        const uint32_t Asb = sbase + (it & 3) * HSTAGE;
        const uint32_t Bsb = Asb + HA_BYTES;

#pragma unroll
        for (int kk = 0; kk < 32; kk += 16) {
            uint32_t af[4][4];
#pragma unroll
            for (int mt = 0; mt < 4; mt++) {
                const int row = wm + mt * 16 + a_lrow;
                ldsm_x4(af[mt][0], af[mt][1], af[mt][2], af[mt][3],
                        Asb + row * HAS_B + kk * 2 + a_lkof);
            }
            uint32_t bf[8][2];
#pragma unroll
            for (int pr = 0; pr < 4; pr++) {
                const int r = kk + b_lrow;
                const int n0 = wn + pr * 16 + b_lnof;
                const uint32_t addr =
                    Bsb + r * 256 + (((n0 >> 3) ^ (r & 7)) * 16);
                ldsm_x4_t(bf[pr * 2][0], bf[pr * 2][1],
                          bf[pr * 2 + 1][0], bf[pr * 2 + 1][1], addr);
            }
#pragma unroll
            for (int mt = 0; mt < 4; mt++)
#pragma unroll
                for (int nt = 0; nt < 8; nt++)
                    mma_f16(acc[mt][nt][0], acc[mt][nt][1],
                            acc[mt][nt][2], acc[mt][nt][3],
                            af[mt][0], af[mt][1], af[mt][2], af[mt][3],
                            bf[nt][0], bf[nt][1]);
        }
        __syncthreads();
    }

#pragma unroll
    for (int mt = 0; mt < 4; mt++) {
#pragma unroll
        for (int nt = 0; nt < 8; nt++) {
            const int col = bn + wn + nt * 8 + 2 * lr;
#pragma unroll
            for (int half_i = 0; half_i < 2; half_i++) {
                const int row = bm + wm + mt * 16 + lq + half_i * 8;
                float v0 = acc[mt][nt][half_i * 2 + 0];
                float v1 = acc[mt][nt][half_i * 2 + 1];
                if (EPI >= 1) {
                    v0 += bias[col];
                    v1 += bias[col + 1];
                }
                if (EPI == 2) {
                    v0 = gelu_exact(v0);
                    v1 = gelu_exact(v1);
                }
                if (OUTH) {
                    __half2 hv = __floats2half2_rn(v0, v1);
                    *(__half2*)((__half*)Cout + (size_t)row * N + col) = hv;
                } else {
                    *(float2*)((float*)Cout + (size_t)row * N + col) =
                        make_float2(v0, v1);
                }
            }
        }
    }
}

// ---------------- fp32 -> fp16 converts -------------------------------------
__global__ __launch_bounds__(256) void cvt_h_kernel(
    const float* __restrict__ in, __half* __restrict__ out)
{
    const size_t i = ((size_t)blockIdx.x * 256 + threadIdx.x) * 4;
    float4 v = *(const float4*)&in[i];
    *(__half2*)&out[i]     = __floats2half2_rn(v.x, v.y);
    *(__half2*)&out[i + 2] = __floats2half2_rn(v.z, v.w);
}

// in: [R][C] fp32; out: [R][ldo] fp16 at column offset coff
__global__ __launch_bounds__(256) void cvt_h_strided_kernel(
    const float* __restrict__ in, __half* __restrict__ out,
    int C, int ldo, int coff)
{
    const size_t i = ((size_t)blockIdx.x * 256 + threadIdx.x) * 4;
    const int r = (int)(i / C);
    const int c = (int)(i % C);
    float4 v = *(const float4*)&in[i];
    __half* o = out + (size_t)r * ldo + coff + c;
    *(__half2*)&o[0] = __floats2half2_rn(v.x, v.y);
    *(__half2*)&o[2] = __floats2half2_rn(v.z, v.w);
}

// ---------------- fp16 flash attention --------------------------------------
// Q/K/V read from one [M][ldqkv] buffer at column offsets 0/Dd/2Dd (+h*64).
static constexpr int FQ_OFF = 0;                 // 128 rows * 128 B = 16 KB
static constexpr int FK_OFF = 16384;             // 2 x 8 KB
static constexpr int FV_OFF = 32768;             // 2 x 8 KB
static constexpr int FH_SMEM = 49152;

__global__ __launch_bounds__(256) void flash_h_kernel(
    const __half* __restrict__ QKV, int ldqkv, __half* __restrict__ Ob)
{
    extern __shared__ __align__(128) char fsm[];
    const uint32_t sbase = smem_u32(fsm);

    const int tid = threadIdx.x;
    const int warp = tid >> 5;
    const int lane = tid & 31;
    const int lq = lane >> 2;
    const int lr = lane & 3;

    const int b = blockIdx.y / Hh;
    const int h = blockIdx.y % Hh;
    const int q0 = blockIdx.x * 128;
    const int w16 = warp * 16;

    const __half* Qb = QKV + h * HDd;
    const __half* Kb = QKV + Dd + h * HDd;
    const __half* Vb = QKV + 2 * Dd + h * HDd;

    int kv_r[2], kv_c[2];
#pragma unroll
    for (int it = 0; it < 2; it++) {
        const int id = tid + it * 256;
        kv_r[it] = id >> 3;
        kv_c[it] = id & 7;
    }

    auto issue_kv = [&](int tile, int buf) {
        const size_t baseKV = ((size_t)(b * Tt + tile * 64)) * ldqkv;
        const uint32_t kst = sbase + FK_OFF + buf * 8192;
        const uint32_t vst = sbase + FV_OFF + buf * 8192;
#pragma unroll
        for (int it = 0; it < 2; it++) {
            const int r = kv_r[it], c = kv_c[it];
            const size_t g = baseKV + (size_t)r * ldqkv + c * 8;
            const uint32_t so = r * 128 + ((c ^ (r & 7)) * 16);
            cp_async16(kst + so, Kb + g);
            cp_async16(vst + so, Vb + g);
        }
        cp_commit();
    };

    issue_kv(0, 0);

    // stage Q tile [128 x 64] (swizzled)
    {
        const size_t baseQ = ((size_t)(b * Tt + q0)) * ldqkv;
#pragma unroll
        for (int it = 0; it < 4; it++) {
            const int id = tid + it * 256;
            const int r = id >> 3, c = id & 7;
            uint4 v = *(const uint4*)&Qb[baseQ + (size_t)r * ldqkv + c * 8];
            *(uint4*)(fsm + FQ_OFF + r * 128 + ((c ^ (r & 7)) * 16)) = v;
        }
    }
    __syncthreads();

    uint32_t qa[4][4];
    {
        const int arow = w16 + (lane & 15);
        const __half2 sc2 = __float2half2_rn(0.125f);
#pragma unroll
        for (int kc = 0; kc < 4; kc++) {
            const int chunk = kc * 2 + (lane >> 4);
            const uint32_t addr =
                sbase + FQ_OFF + arow * 128 + ((chunk ^ (arow & 7)) * 16);
            ldsm_x4(qa[kc][0], qa[kc][1], qa[kc][2], qa[kc][3], addr);
#pragma unroll
            for (int r = 0; r < 4; r++) {
                __half2 t = *(__half2*)&qa[kc][r];
                t = __hmul2(t, sc2);
                qa[kc][r] = *(uint32_t*)&t;
            }
        }
    }

    float o[8][4];
#pragma unroll
    for (int nt = 0; nt < 8; nt++)
#pragma unroll
        for (int r = 0; r < 4; r++) o[nt][r] = 0.0f;
    float m0 = -INFINITY, m1 = -INFINITY;
    float l0 = 0.0f, l1 = 0.0f;

    const int kv_group = lane >> 3;
    const int kv_within = lane & 7;

    const int NT = Tt / 64;
    for (int t = 0; t < NT; ++t) {
        if (t + 1 < NT) issue_kv(t + 1, (t + 1) & 1);
        cp_wait<1>();
        __syncthreads();

        const uint32_t kbase = sbase + FK_OFF + (t & 1) * 8192;
        const uint32_t vbase = sbase + FV_OFF + (t & 1) * 8192;

        float s[8][4];
#pragma unroll
        for (int nt = 0; nt < 8; nt++)
#pragma unroll
            for (int r = 0; r < 4; r++) s[nt][r] = 0.0f;

#pragma unroll
        for (int kc = 0; kc < 4; kc++) {
#pragma unroll
            for (int ntp = 0; ntp < 4; ntp++) {
                const int row = ntp * 16 + (kv_group >> 1) * 8 + kv_within;
                const int chunk = kc * 2 + (kv_group & 1);
                uint32_t b0a, b1a, b0b, b1b;
                ldsm_x4(b0a, b1a, b0b, b1b,
                        kbase + row * 128 + ((chunk ^ (row & 7)) * 16));
                mma_f16(s[ntp * 2][0], s[ntp * 2][1], s[ntp * 2][2], s[ntp * 2][3],
                        qa[kc][0], qa[kc][1], qa[kc][2], qa[kc][3], b0a, b1a);
                mma_f16(s[ntp * 2 + 1][0], s[ntp * 2 + 1][1],
                        s[ntp * 2 + 1][2], s[ntp * 2 + 1][3],
                        qa[kc][0], qa[kc][1], qa[kc][2], qa[kc][3], b0b, b1b);
            }
        }

        float rm0 = -INFINITY, rm1 = -INFINITY;
#pragma unroll
        for (int nt = 0; nt < 8; nt++) {
            rm0 = fmaxf(rm0, fmaxf(s[nt][0], s[nt][1]));
            rm1 = fmaxf(rm1, fmaxf(s[nt][2], s[nt][3]));
        }
        rm0 = fmaxf(rm0, __shfl_xor_sync(0xffffffffu, rm0, 1));
        rm0 = fmaxf(rm0, __shfl_xor_sync(0xffffffffu, rm0, 2));
        rm1 = fmaxf(rm1, __shfl_xor_sync(0xffffffffu, rm1, 1));
        rm1 = fmaxf(rm1, __shfl_xor_sync(0xffffffffu, rm1, 2));
        const float mn0 = fmaxf(m0, rm0);
        const float mn1 = fmaxf(m1, rm1);
        const float alpha0 = __expf(m0 - mn0);
        const float alpha1 = __expf(m1 - mn1);

        float p[8][4];
        float rs0 = 0.0f, rs1 = 0.0f;
#pragma unroll
        for (int nt = 0; nt < 8; nt++) {
            p[nt][0] = __expf(s[nt][0] - mn0);
            p[nt][1] = __expf(s[nt][1] - mn0);
            p[nt][2] = __expf(s[nt][2] - mn1);
            p[nt][3] = __expf(s[nt][3] - mn1);
            rs0 += p[nt][0] + p[nt][1];
            rs1 += p[nt][2] + p[nt][3];
        }
        rs0 += __shfl_xor_sync(0xffffffffu, rs0, 1);
        rs0 += __shfl_xor_sync(0xffffffffu, rs0, 2);
        rs1 += __shfl_xor_sync(0xffffffffu, rs1, 1);
        rs1 += __shfl_xor_sync(0xffffffffu, rs1, 2);

        l0 = l0 * alpha0 + rs0;
        l1 = l1 * alpha1 + rs1;
        m0 = mn0;
        m1 = mn1;
#pragma unroll
        for (int nt = 0; nt < 8; nt++) {
            o[nt][0] *= alpha0; o[nt][1] *= alpha0;
            o[nt][2] *= alpha1; o[nt][3] *= alpha1;
        }

        uint32_t pa[4][4];
#pragma unroll
        for (int kc = 0; kc < 4; kc++) {
            pa[kc][0] = pack_h2(p[2 * kc][0], p[2 * kc][1]);
            pa[kc][1] = pack_h2(p[2 * kc][2], p[2 * kc][3]);
            pa[kc][2] = pack_h2(p[2 * kc + 1][0], p[2 * kc + 1][1]);
            pa[kc][3] = pack_h2(p[2 * kc + 1][2], p[2 * kc + 1][3]);
        }

#pragma unroll
        for (int kc = 0; kc < 4; kc++) {
#pragma unroll
            for (int ntp = 0; ntp < 4; ntp++) {
                const int row = kc * 16 + (kv_group & 1) * 8 + kv_within;
                const int chunk = ntp * 2 + (kv_group >> 1);
                uint32_t v0, v1, v2, v3;
                ldsm_x4_t(v0, v1, v2, v3,
                          vbase + row * 128 + ((chunk ^ (row & 7)) * 16));
                mma_f16(o[ntp * 2][0], o[ntp * 2][1], o[ntp * 2][2], o[ntp * 2][3],
                        pa[kc][0], pa[kc][1], pa[kc][2], pa[kc][3], v0, v1);
                mma_f16(o[ntp * 2 + 1][0], o[ntp * 2 + 1][1],
                        o[ntp * 2 + 1][2], o[ntp * 2 + 1][3],
                        pa[kc][0], pa[kc][1], pa[kc][2], pa[kc][3], v2, v3);
            }
        }
        __syncthreads();
    }

    const float inv0 = 1.0f / l0;
    const float inv1 = 1.0f / l1;
    const int r0 = q0 + w16 + lq;
    const int r1 = r0 + 8;
    const size_t base0 = ((size_t)(b * Tt + r0)) * Dd + h * HDd;
    const size_t base1 = ((size_t)(b * Tt + r1)) * Dd + h * HDd;
#pragma unroll
    for (int nt = 0; nt < 8; nt++) {
        const int c = nt * 8 + 2 * lr;
        *(__half2*)&Ob[base0 + c] =
            __floats2half2_rn(o[nt][0] * inv0, o[nt][1] * inv0);
        *(__half2*)&Ob[base1 + c] =
            __floats2half2_rn(o[nt][2] * inv1, o[nt][3] * inv1);
    }
}

// ---------------- residual add + LayerNorm ---------------------------------
__device__ __forceinline__ float block_sum_1024(float v, float* red) {
    const int tid = threadIdx.x;
    __syncthreads();
#pragma unroll
    for (int o = 16; o > 0; o >>= 1)
        v += __shfl_xor_sync(0xffffffffu, v, o);
    if ((tid & 31) == 0) red[tid >> 5] = v;
    __syncthreads();
    float t = (tid < 8) ? red[tid] : 0.0f;
    if (tid < 32) {
#pragma unroll
        for (int o = 4; o > 0; o >>= 1)
            t += __shfl_xor_sync(0xffffffffu, t, o);
        if (tid == 0) red[0] = t;
    }
    __syncthreads();
    return red[0];
}

__global__ __launch_bounds__(256) void add_ln_kernel(
    const float* __restrict__ A, const float* __restrict__ Bv,
    const float* __restrict__ g, const float* __restrict__ be,
    float* __restrict__ out, __half* __restrict__ outh)
{
    __shared__ float red[8];
    const int row = blockIdx.x;
    const int tid = threadIdx.x;
    const size_t base = (size_t)row * Dd;
    const int c = tid * 4;

    float4 a = *(const float4*)&A[base + c];
    float4 b = *(const float4*)&Bv[base + c];
    float v0 = a.x + b.x, v1 = a.y + b.y, v2 = a.z + b.z, v3 = a.w + b.w;

    float s = block_sum_1024(v0 + v1 + v2 + v3, red);
    const float mu = s * (1.0f / Dd);
    float d0 = v0 - mu, d1 = v1 - mu, d2 = v2 - mu, d3 = v3 - mu;
    float q = block_sum_1024(d0 * d0 + d1 * d1 + d2 * d2 + d3 * d3, red);
    const float inv = rsqrtf(q * (1.0f / Dd) + 1e-5f);

    float4 gv = *(const float4*)&g[c];
    float4 bev = *(const float4*)&be[c];
    float4 o;
    o.x = d0 * inv * gv.x + bev.x;
    o.y = d1 * inv * gv.y + bev.y;
    o.z = d2 * inv * gv.z + bev.z;
    o.w = d3 * inv * gv.w + bev.w;
    *(float4*)&out[base + c] = o;
    if (outh != nullptr) {
        *(__half2*)&outh[base + c]     = __floats2half2_rn(o.x, o.y);
        *(__half2*)&outh[base + c + 2] = __floats2half2_rn(o.z, o.w);
    }
}

// ---------------- orchestration --------------------------------------------
extern "C" void kernel_launch(void* const* d_in, const int* in_sizes, int n_in,
                              void* d_out, int out_size)
{
    const float* x   = (const float*)d_in[0];
    const float* wq  = (const float*)d_in[1];
    const float* wk  = (const float*)d_in[2];
    const float* wv  = (const float*)d_in[3];
    const float* wo  = (const float*)d_in[4];
    const float* w1  = (const float*)d_in[5];
    const float* b1  = (const float*)d_in[6];
    const float* w2  = (const float*)d_in[7];
    const float* b2  = (const float*)d_in[8];
    const float* g1  = (const float*)d_in[9];
    const float* be1 = (const float*)d_in[10];
    const float* g2  = (const float*)d_in[11];
    const float* be2 = (const float*)d_in[12];

    float *proj, *h, *ff2;
    __half *xh, *qkvh, *attnh, *hh, *ff1h, *wqkvh, *woh, *w1h, *w2h;
    cudaGetSymbolAddress((void**)&proj,  g_proj);
    cudaGetSymbolAddress((void**)&h,     g_h);
    cudaGetSymbolAddress((void**)&ff2,   g_ff2);
    cudaGetSymbolAddress((void**)&xh,    g_xh);
    cudaGetSymbolAddress((void**)&qkvh,  g_qkvh);
    cudaGetSymbolAddress((void**)&attnh, g_attnh);
    cudaGetSymbolAddress((void**)&hh,    g_hh);
    cudaGetSymbolAddress((void**)&ff1h,  g_ff1h);
    cudaGetSymbolAddress((void**)&wqkvh, g_wqkvh);
    cudaGetSymbolAddress((void**)&woh,   g_woh);
    cudaGetSymbolAddress((void**)&w1h,   g_w1h);
    cudaGetSymbolAddress((void**)&w2h,   g_w2h);

    cudaFuncSetAttribute(gemm_h_kernel<1, 0>,
                         cudaFuncAttributeMaxDynamicSharedMemorySize, HGEMM_SMEM);
    cudaFuncSetAttribute(gemm_h_kernel<0, 0>,
                         cudaFuncAttributeMaxDynamicSharedMemorySize, HGEMM_SMEM);
    cudaFuncSetAttribute(gemm_h_kernel<1, 2>,
                         cudaFuncAttributeMaxDynamicSharedMemorySize, HGEMM_SMEM);
    cudaFuncSetAttribute(gemm_h_kernel<0, 1>,
                         cudaFuncAttributeMaxDynamicSharedMemorySize, HGEMM_SMEM);
    cudaFuncSetAttribute(flash_h_kernel,
                         cudaFuncAttributeMaxDynamicSharedMemorySize, FH_SMEM);

    auto cvt = [](const float* in, __half* out, size_t n) {
        cvt_h_kernel<<<(unsigned)(n / 1024), 256>>>(in, out);
    };
    cvt(x,  xh,  (size_t)Mrows * Dd);
    // wq/wk/wv -> one [Dd][3*Dd] buffer at column offsets 0/Dd/2Dd
    cvt_h_strided_kernel<<<(unsigned)((size_t)Dd * Dd / 1024), 256>>>(
        wq, wqkvh, Dd, D3, 0);
    cvt_h_strided_kernel<<<(unsigned)((size_t)Dd * Dd / 1024), 256>>>(
        wk, wqkvh, Dd, D3, Dd);
    cvt_h_strided_kernel<<<(unsigned)((size_t)Dd * Dd / 1024), 256>>>(
        wv, wqkvh, Dd, D3, 2 * Dd);
    cvt(wo, woh, (size_t)Dd * Dd);
    cvt(w1, w1h, (size_t)Dd * DFf);
    cvt(w2, w2h, (size_t)DFf * Dd);

    const dim3 gblk(128);
    const dim3 gQKV(D3  / 128, Mrows / 128);  // (24, 64)
    const dim3 gD  (Dd  / 128, Mrows / 128);  // (8, 64)
    const dim3 gDF (DFf / 128, Mrows / 128);  // (32, 64)

    // fused QKV: [Mrows][3072] fp16
    gemm_h_kernel<1, 0><<<gQKV, gblk, HGEMM_SMEM>>>(xh, wqkvh, nullptr, qkvh,
                                                    Mrows, D3, Dd);

    flash_h_kernel<<<dim3(Tt / 128, Bb * Hh), dim3(256), FH_SMEM>>>(qkvh, D3, attnh);

    gemm_h_kernel<0, 0><<<gD, gblk, HGEMM_SMEM>>>(attnh, woh, nullptr, proj,
                                                  Mrows, Dd, Dd);

    add_ln_kernel<<<Mrows, 256>>>(x, proj, g1, be1, h, hh);

    gemm_h_kernel<1, 2><<<gDF, gblk, HGEMM_SMEM>>>(hh, w1h, b1, ff1h, Mrows, DFf, Dd);
    gemm_h_kernel<0, 1><<<gD,  gblk, HGEMM_SMEM>>>(ff1h, w2h, b2, ff2, Mrows, Dd, DFf);

    add_ln_kernel<<<Mrows, 256>>>(h, ff2, g2, be2, (float*)d_out, nullptr);
}